// round 8
// baseline (speedup 1.0000x reference)
#include <cuda_runtime.h>
#include <math.h>
#include <float.h>
#include <stdint.h>

// ---------------- problem constants (fixed by dataset) ----------------
#define N_Q   65      // n = 1+W
#define M_KV  129     // m = 1+R
#define NH    8       // heads
#define HDIM  64      // head dim
#define CDIM  512     // model dim (= H*HD)
#define BQMAX 512     // B_ = 512

// ---------------- scratch (device globals; no allocation) -------------
__device__ float g_q  [(size_t)BQMAX * N_Q  * CDIM];        // (B_, n, H*HD)
__device__ float g_kv [(size_t)BQMAX * M_KV * 2 * CDIM];    // (B_, m, 2*H*HD)
__device__ float g_att[(size_t)BQMAX * N_Q  * CDIM];        // (B_, n, H*HD)

// ---------------- small helpers ----------------------------------------
__device__ __forceinline__ float tf32r(float f) {
    uint32_t u;
    asm("cvt.rna.tf32.f32 %0, %1;" : "=r"(u) : "f"(f));
    return __uint_as_float(u);
}
__device__ __forceinline__ uint32_t tf32u(float f) {
    uint32_t u;
    asm("cvt.rna.tf32.f32 %0, %1;" : "=r"(u) : "f"(f));
    return u;
}
__device__ __forceinline__ void mma_tf32(float c[4], const uint32_t a[4],
                                         const uint32_t b[2]) {
    asm volatile(
        "mma.sync.aligned.m16n8k8.row.col.f32.tf32.tf32.f32 "
        "{%0,%1,%2,%3}, {%4,%5,%6,%7}, {%8,%9}, {%0,%1,%2,%3};"
        : "+f"(c[0]), "+f"(c[1]), "+f"(c[2]), "+f"(c[3])
        : "r"(a[0]), "r"(a[1]), "r"(a[2]), "r"(a[3]),
          "r"(b[0]), "r"(b[1]));
}
__device__ __forceinline__ void cp16(float* smem, const float* g) {
    uint32_t a = (uint32_t)__cvta_generic_to_shared(smem);
    asm volatile("cp.async.cg.shared.global [%0], [%1], 16;\n"
                 :: "r"(a), "l"(g));
}

// =======================================================================
// TF32 tensor-core GEMM, cp.async 2-stage pipeline, big warp tiles.
//   C[M,N] = A[M,K] @ W[N,K]^T + bias[N]
// BM=128, BN=256, BK=32, 256 threads (8 warps, 2(M) x 4(N)),
// warp tile 64x64 (4x8 m16n8k8) for deep ILP.
// Requires M%128==0, N%256==0, K%32==0.
// =======================================================================
#define GBM 128
#define GBN 256
#define GBK 32
#define GST 36                       // smem row stride (words) -> conflict-free
#define A_WORDS (GBM * GST)          // 4608
#define B_WORDS (GBN * GST)          // 9216
#define STAGE_WORDS (A_WORDS + B_WORDS)
#define GEMM_SMEM_BYTES (2 * STAGE_WORDS * 4)   // 110592

__global__ __launch_bounds__(256, 1) void gemm_tf32_kernel(
    const float* __restrict__ A, const float* __restrict__ W,
    const float* __restrict__ bias, float* __restrict__ C,
    int K, int N)
{
    extern __shared__ float smg[];
    // stage s: A at s*STAGE_WORDS, B at s*STAGE_WORDS + A_WORDS

    const int tid    = threadIdx.x;
    const int warp   = tid >> 5;
    const int lane   = tid & 31;
    const int quad   = lane >> 2;
    const int tq     = lane & 3;
    const int warp_m = warp & 1;           // 0..1  (64 rows each)
    const int warp_n = warp >> 1;          // 0..3  (64 cols each)
    const int rowBase = blockIdx.y * GBM;
    const int colBase = blockIdx.x * GBN;

    const float* Aptr = A + (size_t)rowBase * K;
    const float* Wptr = W + (size_t)colBase * K;

    float acc[4][8][4];
#pragma unroll
    for (int mt = 0; mt < 4; mt++)
#pragma unroll
        for (int nt = 0; nt < 8; nt++)
#pragma unroll
            for (int r = 0; r < 4; r++) acc[mt][nt][r] = 0.f;

    const int NITER = K >> 5;

    // issue cp.async loads for iteration `it` into stage (it&1)
    auto issue = [&](int it) {
        float* As = smg + (it & 1) * STAGE_WORDS;
        float* Bs = As + A_WORDS;
        const int k0 = it * GBK;
        // A: 128 x 32 = 1024 float4, 4 per thread
#pragma unroll
        for (int i = 0; i < 4; i++) {
            int f  = tid + i * 256;
            int rr = f >> 3;
            int c4 = (f & 7) << 2;
            cp16(As + rr * GST + c4, Aptr + (size_t)rr * K + k0 + c4);
        }
        // B: 256 x 32 = 2048 float4, 8 per thread
#pragma unroll
        for (int i = 0; i < 8; i++) {
            int f  = tid + i * 256;
            int rr = f >> 3;
            int c4 = (f & 7) << 2;
            cp16(Bs + rr * GST + c4, Wptr + (size_t)rr * K + k0 + c4);
        }
    };

    issue(0);
    asm volatile("cp.async.commit_group;\n");

    for (int it = 0; it < NITER; it++) {
        if (it + 1 < NITER) {
            issue(it + 1);
            asm volatile("cp.async.commit_group;\n");
            asm volatile("cp.async.wait_group 1;\n");
        } else {
            asm volatile("cp.async.wait_group 0;\n");
        }
        __syncthreads();

        const float* as = smg + (it & 1) * STAGE_WORDS;
        const float* bs = as + A_WORDS;

#pragma unroll
        for (int ks = 0; ks < 4; ks++) {
            const int kcol = ks * 8 + tq;
            uint32_t af[4][4];
            uint32_t bf[8][2];
#pragma unroll
            for (int mt = 0; mt < 4; mt++) {
                int r = warp_m * 64 + mt * 16 + quad;
                af[mt][0] = tf32u(as[r * GST + kcol]);
                af[mt][1] = tf32u(as[(r + 8) * GST + kcol]);
                af[mt][2] = tf32u(as[r * GST + kcol + 4]);
                af[mt][3] = tf32u(as[(r + 8) * GST + kcol + 4]);
            }
#pragma unroll
            for (int nt = 0; nt < 8; nt++) {
                int r = warp_n * 64 + nt * 8 + quad;
                bf[nt][0] = tf32u(bs[r * GST + kcol]);
                bf[nt][1] = tf32u(bs[r * GST + kcol + 4]);
            }
#pragma unroll
            for (int mt = 0; mt < 4; mt++)
#pragma unroll
                for (int nt = 0; nt < 8; nt++)
                    mma_tf32(acc[mt][nt], af[mt], bf[nt]);
        }
        __syncthreads();
    }

    // ---- epilogue: bias + store
#pragma unroll
    for (int mt = 0; mt < 4; mt++) {
        int r0 = rowBase + warp_m * 64 + mt * 16 + quad;
#pragma unroll
        for (int nt = 0; nt < 8; nt++) {
            int c = colBase + warp_n * 64 + nt * 8 + 2 * tq;
            float2 bv = *(const float2*)&bias[c];
            float2 o0, o1;
            o0.x = acc[mt][nt][0] + bv.x;
            o0.y = acc[mt][nt][1] + bv.y;
            o1.x = acc[mt][nt][2] + bv.x;
            o1.y = acc[mt][nt][3] + bv.y;
            *(float2*)&C[(size_t)r0 * N + c]       = o0;
            *(float2*)&C[(size_t)(r0 + 8) * N + c] = o1;
        }
    }
}

// =======================================================================
// Tensorized fused window attention (unchanged from R6, known-good)
// =======================================================================
#define QS 68
#define KS 68
#define SS 140
#define VS 140
#define OFF_KV  9100
#define OFF_BR  (OFF_KV + 144 * KS)
#define OFF_BU  (OFF_BR + 191)
#define OFF_BD  (OFF_BU + 128)
#define OFF_BSF (OFF_BD + 64)
#define ATTN_WORDS (OFF_BSF + 1)
#define ATTN_SMEM_BYTES (ATTN_WORDS * 4)

__global__ __launch_bounds__(256, 2) void attn_kernel(
    const float* __restrict__ rel_table,
    const float* __restrict__ cls_self,
    const float* __restrict__ cls_up,
    const float* __restrict__ cls_down,
    const int*   __restrict__ mask_left,
    const int*   __restrict__ mask_right,
    const int*   __restrict__ nW_ptr,
    float* __restrict__ out)
{
    extern __shared__ float sm[];
    float* Sq  = sm;
    float* KV  = sm + OFF_KV;
    float* brl = sm + OFF_BR;
    float* bup = sm + OFF_BU;
    float* bdn = sm + OFF_BD;
    float* bsf = sm + OFF_BSF;

    const int bid  = blockIdx.x;
    const int b    = bid >> 3;
    const int h    = bid & 7;
    const int tid  = threadIdx.x;
    const int warp = tid >> 5;
    const int lane = tid & 31;
    const int quad = lane >> 2;
    const int tq   = lane & 3;
    const int wm   = warp >> 1;
    const int wn   = warp & 1;
    const int nW   = *nW_ptr;

    if (tid < 191) brl[tid] = rel_table[tid * NH + h];
    if (tid < 128) bup[tid] = cls_up[h * 128 + tid];
    if (tid < 64)  bdn[tid] = cls_down[h * 64 + tid];
    if (tid == 224) bsf[0]  = cls_self[h];

    for (int idx = tid; idx < N_Q * 16; idx += 256) {
        int i = idx >> 4, c4 = (idx & 15) << 2;
        float4 v = *(const float4*)&g_q[((size_t)(b * N_Q + i)) * CDIM + h * HDIM + c4];
        float4 t = { tf32r(v.x), tf32r(v.y), tf32r(v.z), tf32r(v.w) };
        *(float4*)&Sq[i * QS + c4] = t;
    }
    for (int idx = tid; idx < 144 * 16; idx += 256) {
        int j = idx >> 4, c4 = (idx & 15) << 2;
        float4 t = {0.f, 0.f, 0.f, 0.f};
        if (j < M_KV) {
            float4 v = *(const float4*)&g_kv[((size_t)(b * M_KV + j)) * (2 * CDIM)
                                             + h * HDIM + c4];
            t.x = tf32r(v.x); t.y = tf32r(v.y); t.z = tf32r(v.z); t.w = tf32r(v.w);
        }
        *(float4*)&KV[j * KS + c4] = t;
    }
    __syncthreads();

    const int nbase = wn * 72;
    float acc[9][4];
#pragma unroll
    for (int nt = 0; nt < 9; nt++)
#pragma unroll
        for (int r = 0; r < 4; r++) acc[nt][r] = 0.f;

#pragma unroll
    for (int ks = 0; ks < 8; ks++) {
        const int kc = ks * 8 + tq;
        const int row = wm * 16 + quad;
        uint32_t a[4];
        a[0] = __float_as_uint(Sq[row * QS + kc]);
        a[1] = __float_as_uint(Sq[(row + 8) * QS + kc]);
        a[2] = __float_as_uint(Sq[row * QS + kc + 4]);
        a[3] = __float_as_uint(Sq[(row + 8) * QS + kc + 4]);
#pragma unroll
        for (int nt = 0; nt < 9; nt++) {
            int jr = nbase + nt * 8 + quad;
            uint32_t bfr[2];
            bfr[0] = __float_as_uint(KV[jr * KS + kc]);
            bfr[1] = __float_as_uint(KV[jr * KS + kc + 4]);
            mma_tf32(acc[nt], a, bfr);
        }
    }

    float s64 = 0.f;
    if (tid < M_KV) {
#pragma unroll 8
        for (int d = 0; d < HDIM; d++)
            s64 += Sq[64 * QS + d] * KV[tid * KS + d];
    }
    __syncthreads();

    const int mc   = (nW < 4) ? nW : 4;
    const int w    = b % nW;
    const bool hasL = (w < mc);
    const bool hasR = (w >= nW - mc);
    const int* mlp = mask_left  + (size_t)w * N_Q * M_KV;
    const int* mrp = mask_right + (size_t)(w - nW + 4) * N_Q * M_KV;

#pragma unroll
    for (int nt = 0; nt < 9; nt++) {
        int j0 = nbase + nt * 8 + 2 * tq;
        int i0 = wm * 16 + quad;
#pragma unroll
        for (int e = 0; e < 4; e++) {
            int i = i0 + (e >> 1) * 8;
            int j = j0 + (e & 1);
            if (j >= M_KV) continue;
            float bias;
            if (i == 0)      bias = (j == 0) ? bsf[0] : bup[j - 1];
            else if (j == 0) bias = bdn[i - 1];
            else             bias = brl[i - j + 127];
            float s = acc[nt][e] * 0.125f + bias;
            if (hasL && mlp[i * M_KV + j] == 1) s = -FLT_MAX;
            if (hasR && mrp[i * M_KV + j] == 1) s = -FLT_MAX;
            Sq[i * SS + j] = s;
        }
    }
    if (tid < M_KV) {
        int j = tid;
        float bias = (j == 0) ? bdn[63] : brl[64 - j + 127];
        float s = s64 * 0.125f + bias;
        if (hasL && mlp[64 * M_KV + j] == 1) s = -FLT_MAX;
        if (hasR && mrp[64 * M_KV + j] == 1) s = -FLT_MAX;
        Sq[64 * SS + j] = s;
    }
    for (int idx = tid; idx < N_Q * 11; idx += 256) {
        int i = idx / 11, c = M_KV + idx % 11;
        Sq[i * SS + c] = 0.f;
    }
    for (int idx = tid; idx < 136 * HDIM; idx += 256) {
        int j = idx >> 6, d = idx & 63;
        float v = 0.f;
        if (j < M_KV)
            v = tf32r(g_kv[((size_t)(b * M_KV + j)) * (2 * CDIM) + CDIM + h * HDIM + d]);
        KV[d * VS + j] = v;
    }
    __syncthreads();

    for (int r = warp; r < N_Q; r += 8) {
        float mx = -FLT_MAX;
        for (int c = lane; c < M_KV; c += 32) mx = fmaxf(mx, Sq[r * SS + c]);
#pragma unroll
        for (int o = 16; o; o >>= 1) mx = fmaxf(mx, __shfl_xor_sync(0xffffffffu, mx, o));
        float sum = 0.f;
        float ev[5];
#pragma unroll
        for (int t = 0; t < 5; t++) {
            int c = lane + t * 32;
            float e = (c < M_KV) ? expf(Sq[r * SS + c] - mx) : 0.f;
            ev[t] = e;
            sum += e;
        }
#pragma unroll
        for (int o = 16; o; o >>= 1) sum += __shfl_xor_sync(0xffffffffu, sum, o);
        float inv = 1.0f / sum;
#pragma unroll
        for (int t = 0; t < 5; t++) {
            int c = lane + t * 32;
            if (c < M_KV) Sq[r * SS + c] = tf32r(ev[t] * inv);
        }
    }
    __syncthreads();

    float acc2[4][4];
#pragma unroll
    for (int nt = 0; nt < 4; nt++)
#pragma unroll
        for (int r = 0; r < 4; r++) acc2[nt][r] = 0.f;

#pragma unroll
    for (int ks = 0; ks < 17; ks++) {
        const int kc = ks * 8 + tq;
        const int row = wm * 16 + quad;
        uint32_t a[4];
        a[0] = __float_as_uint(Sq[row * SS + kc]);
        a[1] = __float_as_uint(Sq[(row + 8) * SS + kc]);
        a[2] = __float_as_uint(Sq[row * SS + kc + 4]);
        a[3] = __float_as_uint(Sq[(row + 8) * SS + kc + 4]);
#pragma unroll
        for (int nt = 0; nt < 4; nt++) {
            int dr = wn * 32 + nt * 8 + quad;
            uint32_t bfr[2];
            bfr[0] = __float_as_uint(KV[dr * VS + kc]);
            bfr[1] = __float_as_uint(KV[dr * VS + kc + 4]);
            mma_tf32(acc2[nt], a, bfr);
        }
    }

    float o64 = 0.f;
    if (tid < HDIM) {
        for (int j = 0; j < M_KV; j++)
            o64 += Sq[64 * SS + j] * KV[tid * VS + j];
    }

#pragma unroll
    for (int nt = 0; nt < 4; nt++) {
        int i0 = wm * 16 + quad;
        int d0 = wn * 32 + nt * 8 + 2 * tq;
        float2 o0 = { acc2[nt][0], acc2[nt][1] };
        float2 o1 = { acc2[nt][2], acc2[nt][3] };
        *(float2*)&out[((size_t)(b * N_Q + i0)) * CDIM + h * HDIM + d0]     = o0;
        *(float2*)&out[((size_t)(b * N_Q + i0 + 8)) * CDIM + h * HDIM + d0] = o1;
    }
    if (tid < HDIM)
        out[((size_t)(b * N_Q + 64)) * CDIM + h * HDIM + tid] = o64;
}

// =======================================================================
// kernel_launch
// =======================================================================
extern "C" void kernel_launch(void* const* d_in, const int* in_sizes, int n_in,
                              void* d_out, int out_size)
{
    const float* x    = (const float*)d_in[0];
    const float* x_   = (const float*)d_in[1];
    const int*   mask_left  = (const int*)d_in[2];
    const int*   mask_right = (const int*)d_in[3];
    const int*   nW   = (const int*)d_in[4];
    const float* rel_table = (const float*)d_in[5];
    const float* cls_self  = (const float*)d_in[6];
    const float* cls_up    = (const float*)d_in[7];
    const float* cls_down  = (const float*)d_in[8];
    const float* Wq   = (const float*)d_in[9];
    const float* bq   = (const float*)d_in[10];
    const float* Wkv  = (const float*)d_in[11];
    const float* bkv  = (const float*)d_in[12];
    const float* Wp   = (const float*)d_in[13];
    const float* bp   = (const float*)d_in[14];
    float* out = (float*)d_out;

    const int Bq = in_sizes[0] / (N_Q * CDIM);   // 512

    float *qptr, *kvptr, *aptr;
    cudaGetSymbolAddress((void**)&qptr,  g_q);
    cudaGetSymbolAddress((void**)&kvptr, g_kv);
    cudaGetSymbolAddress((void**)&aptr,  g_att);

    cudaFuncSetAttribute(gemm_tf32_kernel,
                         cudaFuncAttributeMaxDynamicSharedMemorySize,
                         GEMM_SMEM_BYTES);
    cudaFuncSetAttribute(attn_kernel,
                         cudaFuncAttributeMaxDynamicSharedMemorySize,
                         ATTN_SMEM_BYTES);

    // 1) q = x @ Wq^T + bq : M = 33280, N = 512, K = 512
    {
        dim3 grid(CDIM / GBN, (Bq * N_Q) / GBM);       // (2, 260)
        gemm_tf32_kernel<<<grid, 256, GEMM_SMEM_BYTES>>>(x, Wq, bq, qptr, CDIM, CDIM);
    }
    // 2) kv = x_ @ Wkv^T + bkv : M = 66048, N = 1024, K = 512
    {
        dim3 grid((2 * CDIM) / GBN, (Bq * M_KV) / GBM); // (4, 516)
        gemm_tf32_kernel<<<grid, 256, GEMM_SMEM_BYTES>>>(x_, Wkv, bkv, kvptr, CDIM, 2 * CDIM);
    }
    // 3) fused tensorized attention -> g_att
    {
        attn_kernel<<<Bq * NH, 256, ATTN_SMEM_BYTES>>>(
            rel_table, cls_self, cls_up, cls_down,
            mask_left, mask_right, nW, aptr);
    }
    // 4) out = g_att @ Wp^T + bp : M = 33280, N = 512, K = 512
    {
        dim3 grid(CDIM / GBN, (Bq * N_Q) / GBM);
        gemm_tf32_kernel<<<grid, 256, GEMM_SMEM_BYTES>>>(aptr, Wp, bp, out, CDIM, CDIM);
    }
}

// round 9
// speedup vs baseline: 1.0354x; 1.0354x over previous
#include <cuda_runtime.h>
#include <math.h>
#include <float.h>
#include <stdint.h>

// ---------------- problem constants (fixed by dataset) ----------------
#define N_Q   65      // n = 1+W
#define M_KV  129     // m = 1+R
#define NH    8       // heads
#define HDIM  64      // head dim
#define CDIM  512     // model dim (= H*HD)
#define BQMAX 512     // B_ = 512

// ---------------- scratch (device globals; no allocation) -------------
__device__ float g_q  [(size_t)BQMAX * N_Q  * CDIM];        // (B_, n, H*HD)
__device__ float g_kv [(size_t)BQMAX * M_KV * 2 * CDIM];    // (B_, m, 2*H*HD)
__device__ float g_att[(size_t)BQMAX * N_Q  * CDIM];        // (B_, n, H*HD)

// ---------------- small helpers ----------------------------------------
__device__ __forceinline__ float tf32r(float f) {
    uint32_t u;
    asm("cvt.rna.tf32.f32 %0, %1;" : "=r"(u) : "f"(f));
    return __uint_as_float(u);
}
__device__ __forceinline__ void mma_tf32(float c[4], const uint32_t a[4],
                                         const uint32_t b[2]) {
    asm volatile(
        "mma.sync.aligned.m16n8k8.row.col.f32.tf32.tf32.f32 "
        "{%0,%1,%2,%3}, {%4,%5,%6,%7}, {%8,%9}, {%0,%1,%2,%3};"
        : "+f"(c[0]), "+f"(c[1]), "+f"(c[2]), "+f"(c[3])
        : "r"(a[0]), "r"(a[1]), "r"(a[2]), "r"(a[3]),
          "r"(b[0]), "r"(b[1]));
}

// =======================================================================
// TF32 tensor-core GEMM, fragment-packed smem, producer-side cvt.
//   C[M,N] = A[M,K] @ W[N,K]^T + bias[N]
// BM=128, BN=128, BK=32, 256 threads (8 warps = 2(M) x 4(N)),
// warp tile 64x32 (4x4 m16n8k8). 2 CTAs/SM.
//
// Packed A layout: group (g, ks), g = row/16, ks = k-step (0..3).
//   word offset = (g*4+ks)*132 + lane*4 + {0: (quad,kc), 1: (quad+8,kc),
//                                          2: (quad,kc+4), 3: (quad+8,kc+4)}
//   -> consumer fragment = one LDS.128 per (mt, ks).
// Packed B layout: group (g2, ks), g2 = row/8.
//   word offset = (g2*4+ks)*66 + lane*2 + {0: (quad,kc), 1: (quad,kc+4)}
//   -> consumer fragment = one LDS.64 per (nt, ks).
// Fragment values identical to the verified R6 mapping.
// Requires M%128==0, N%128==0, K%32==0.
// =======================================================================
#define GBM 128
#define GBN 128
#define GBK 32
#define A_GRP 132                  // words per (g,ks) A group (128 + pad 4)
#define B_GRP 66                   // words per (g2,ks) B group (64 + pad 2)
#define A_WORDS (32 * A_GRP)       // 8 g  x 4 ks = 4224 words
#define B_WORDS (64 * B_GRP)       // 16 g2 x 4 ks = 4224 words
#define GEMM_SMEM_BYTES ((A_WORDS + B_WORDS) * 4)   // 33792

__global__ __launch_bounds__(256, 2) void gemm_tf32_kernel(
    const float* __restrict__ A, const float* __restrict__ W,
    const float* __restrict__ bias, float* __restrict__ C,
    int K, int N)
{
    extern __shared__ float smg[];
    float* As = smg;
    float* Bs = smg + A_WORDS;

    const int tid    = threadIdx.x;
    const int warp   = tid >> 5;
    const int lane   = tid & 31;
    const int quad   = lane >> 2;
    const int tq     = lane & 3;
    const int warp_m = warp >> 2;          // 0..1 (64 rows)
    const int warp_n = warp & 3;           // 0..3 (32 cols)
    const int rowBase = blockIdx.y * GBM;
    const int colBase = blockIdx.x * GBN;

    const float* Aptr = A + (size_t)rowBase * K;
    const float* Wptr = W + (size_t)colBase * K;

    float acc[4][4][4];
#pragma unroll
    for (int mt = 0; mt < 4; mt++)
#pragma unroll
        for (int nt = 0; nt < 4; nt++)
#pragma unroll
            for (int r = 0; r < 4; r++) acc[mt][nt][r] = 0.f;

    // producer indexing (constant across iterations)
    const int pr  = tid >> 3;              // base row for i=0 (rows step +32/i)
    const int pc4 = tid & 7;               // float4 column within 32-k tile
    const int pks = pc4 >> 1;
    const int pp4 = pc4 & 1;

    const int NITER = K >> 5;

    for (int it = 0; it < NITER; it++) {
        const int k0 = it * GBK;

        // ---- produce A: 128 rows x 32 k, cvt.rna once, packed scatter
#pragma unroll
        for (int i = 0; i < 4; i++) {
            int r = pr + i * 32;
            float4 v = *(const float4*)(Aptr + (size_t)r * K + k0 + pc4 * 4);
            int g  = r >> 4;
            int qq = r & 7;
            int hi = (r >> 3) & 1;
            float* dst = As + (g * 4 + pks) * A_GRP + hi + 2 * pp4;
            dst[(qq * 4 + 0) * 4] = tf32r(v.x);
            dst[(qq * 4 + 1) * 4] = tf32r(v.y);
            dst[(qq * 4 + 2) * 4] = tf32r(v.z);
            dst[(qq * 4 + 3) * 4] = tf32r(v.w);
        }
        // ---- produce B: 128 rows x 32 k
#pragma unroll
        for (int i = 0; i < 4; i++) {
            int r = pr + i * 32;
            float4 v = *(const float4*)(Wptr + (size_t)r * K + k0 + pc4 * 4);
            int g2 = r >> 3;
            int qq = r & 7;
            float* dst = Bs + (g2 * 4 + pks) * B_GRP + pp4;
            dst[(qq * 4 + 0) * 2] = tf32r(v.x);
            dst[(qq * 4 + 1) * 2] = tf32r(v.y);
            dst[(qq * 4 + 2) * 2] = tf32r(v.z);
            dst[(qq * 4 + 3) * 2] = tf32r(v.w);
        }
        __syncthreads();

        // ---- math: 4 ks-steps, fragments via wide LDS
#pragma unroll
        for (int ks = 0; ks < 4; ks++) {
            uint32_t af[4][4];
            uint32_t bf[4][2];
#pragma unroll
            for (int mt = 0; mt < 4; mt++) {
                int g = warp_m * 4 + mt;
                uint4 a4 = *(const uint4*)&As[(g * 4 + ks) * A_GRP + lane * 4];
                af[mt][0] = a4.x; af[mt][1] = a4.y;
                af[mt][2] = a4.z; af[mt][3] = a4.w;
            }
#pragma unroll
            for (int nt = 0; nt < 4; nt++) {
                int g2 = warp_n * 4 + nt;
                uint2 b2 = *(const uint2*)&Bs[(g2 * 4 + ks) * B_GRP + lane * 2];
                bf[nt][0] = b2.x; bf[nt][1] = b2.y;
            }
#pragma unroll
            for (int mt = 0; mt < 4; mt++)
#pragma unroll
                for (int nt = 0; nt < 4; nt++)
                    mma_tf32(acc[mt][nt], af[mt], bf[nt]);
        }
        __syncthreads();
    }

    // ---- epilogue: bias + store
#pragma unroll
    for (int mt = 0; mt < 4; mt++) {
        int r0 = rowBase + warp_m * 64 + mt * 16 + quad;
#pragma unroll
        for (int nt = 0; nt < 4; nt++) {
            int c = colBase + warp_n * 32 + nt * 8 + 2 * tq;
            float2 bv = *(const float2*)&bias[c];
            float2 o0, o1;
            o0.x = acc[mt][nt][0] + bv.x;
            o0.y = acc[mt][nt][1] + bv.y;
            o1.x = acc[mt][nt][2] + bv.x;
            o1.y = acc[mt][nt][3] + bv.y;
            *(float2*)&C[(size_t)r0 * N + c]       = o0;
            *(float2*)&C[(size_t)(r0 + 8) * N + c] = o1;
        }
    }
}

// =======================================================================
// Tensorized fused window attention (unchanged, known-good)
// =======================================================================
#define QS 68
#define KS 68
#define SS 140
#define VS 140
#define OFF_KV  9100
#define OFF_BR  (OFF_KV + 144 * KS)
#define OFF_BU  (OFF_BR + 191)
#define OFF_BD  (OFF_BU + 128)
#define OFF_BSF (OFF_BD + 64)
#define ATTN_WORDS (OFF_BSF + 1)
#define ATTN_SMEM_BYTES (ATTN_WORDS * 4)

__global__ __launch_bounds__(256, 2) void attn_kernel(
    const float* __restrict__ rel_table,
    const float* __restrict__ cls_self,
    const float* __restrict__ cls_up,
    const float* __restrict__ cls_down,
    const int*   __restrict__ mask_left,
    const int*   __restrict__ mask_right,
    const int*   __restrict__ nW_ptr,
    float* __restrict__ out)
{
    extern __shared__ float sm[];
    float* Sq  = sm;
    float* KV  = sm + OFF_KV;
    float* brl = sm + OFF_BR;
    float* bup = sm + OFF_BU;
    float* bdn = sm + OFF_BD;
    float* bsf = sm + OFF_BSF;

    const int bid  = blockIdx.x;
    const int b    = bid >> 3;
    const int h    = bid & 7;
    const int tid  = threadIdx.x;
    const int warp = tid >> 5;
    const int lane = tid & 31;
    const int quad = lane >> 2;
    const int tq   = lane & 3;
    const int wm   = warp >> 1;
    const int wn   = warp & 1;
    const int nW   = *nW_ptr;

    if (tid < 191) brl[tid] = rel_table[tid * NH + h];
    if (tid < 128) bup[tid] = cls_up[h * 128 + tid];
    if (tid < 64)  bdn[tid] = cls_down[h * 64 + tid];
    if (tid == 224) bsf[0]  = cls_self[h];

    for (int idx = tid; idx < N_Q * 16; idx += 256) {
        int i = idx >> 4, c4 = (idx & 15) << 2;
        float4 v = *(const float4*)&g_q[((size_t)(b * N_Q + i)) * CDIM + h * HDIM + c4];
        float4 t = { tf32r(v.x), tf32r(v.y), tf32r(v.z), tf32r(v.w) };
        *(float4*)&Sq[i * QS + c4] = t;
    }
    for (int idx = tid; idx < 144 * 16; idx += 256) {
        int j = idx >> 4, c4 = (idx & 15) << 2;
        float4 t = {0.f, 0.f, 0.f, 0.f};
        if (j < M_KV) {
            float4 v = *(const float4*)&g_kv[((size_t)(b * M_KV + j)) * (2 * CDIM)
                                             + h * HDIM + c4];
            t.x = tf32r(v.x); t.y = tf32r(v.y); t.z = tf32r(v.z); t.w = tf32r(v.w);
        }
        *(float4*)&KV[j * KS + c4] = t;
    }
    __syncthreads();

    const int nbase = wn * 72;
    float acc[9][4];
#pragma unroll
    for (int nt = 0; nt < 9; nt++)
#pragma unroll
        for (int r = 0; r < 4; r++) acc[nt][r] = 0.f;

#pragma unroll
    for (int ks = 0; ks < 8; ks++) {
        const int kc = ks * 8 + tq;
        const int row = wm * 16 + quad;
        uint32_t a[4];
        a[0] = __float_as_uint(Sq[row * QS + kc]);
        a[1] = __float_as_uint(Sq[(row + 8) * QS + kc]);
        a[2] = __float_as_uint(Sq[row * QS + kc + 4]);
        a[3] = __float_as_uint(Sq[(row + 8) * QS + kc + 4]);
#pragma unroll
        for (int nt = 0; nt < 9; nt++) {
            int jr = nbase + nt * 8 + quad;
            uint32_t bfr[2];
            bfr[0] = __float_as_uint(KV[jr * KS + kc]);
            bfr[1] = __float_as_uint(KV[jr * KS + kc + 4]);
            mma_tf32(acc[nt], a, bfr);
        }
    }

    float s64 = 0.f;
    if (tid < M_KV) {
#pragma unroll 8
        for (int d = 0; d < HDIM; d++)
            s64 += Sq[64 * QS + d] * KV[tid * KS + d];
    }
    __syncthreads();

    const int mc   = (nW < 4) ? nW : 4;
    const int w    = b % nW;
    const bool hasL = (w < mc);
    const bool hasR = (w >= nW - mc);
    const int* mlp = mask_left  + (size_t)w * N_Q * M_KV;
    const int* mrp = mask_right + (size_t)(w - nW + 4) * N_Q * M_KV;

#pragma unroll
    for (int nt = 0; nt < 9; nt++) {
        int j0 = nbase + nt * 8 + 2 * tq;
        int i0 = wm * 16 + quad;
#pragma unroll
        for (int e = 0; e < 4; e++) {
            int i = i0 + (e >> 1) * 8;
            int j = j0 + (e & 1);
            if (j >= M_KV) continue;
            float bias;
            if (i == 0)      bias = (j == 0) ? bsf[0] : bup[j - 1];
            else if (j == 0) bias = bdn[i - 1];
            else             bias = brl[i - j + 127];
            float s = acc[nt][e] * 0.125f + bias;
            if (hasL && mlp[i * M_KV + j] == 1) s = -FLT_MAX;
            if (hasR && mrp[i * M_KV + j] == 1) s = -FLT_MAX;
            Sq[i * SS + j] = s;
        }
    }
    if (tid < M_KV) {
        int j = tid;
        float bias = (j == 0) ? bdn[63] : brl[64 - j + 127];
        float s = s64 * 0.125f + bias;
        if (hasL && mlp[64 * M_KV + j] == 1) s = -FLT_MAX;
        if (hasR && mrp[64 * M_KV + j] == 1) s = -FLT_MAX;
        Sq[64 * SS + j] = s;
    }
    for (int idx = tid; idx < N_Q * 11; idx += 256) {
        int i = idx / 11, c = M_KV + idx % 11;
        Sq[i * SS + c] = 0.f;
    }
    for (int idx = tid; idx < 136 * HDIM; idx += 256) {
        int j = idx >> 6, d = idx & 63;
        float v = 0.f;
        if (j < M_KV)
            v = tf32r(g_kv[((size_t)(b * M_KV + j)) * (2 * CDIM) + CDIM + h * HDIM + d]);
        KV[d * VS + j] = v;
    }
    __syncthreads();

    for (int r = warp; r < N_Q; r += 8) {
        float mx = -FLT_MAX;
        for (int c = lane; c < M_KV; c += 32) mx = fmaxf(mx, Sq[r * SS + c]);
#pragma unroll
        for (int o = 16; o; o >>= 1) mx = fmaxf(mx, __shfl_xor_sync(0xffffffffu, mx, o));
        float sum = 0.f;
        float ev[5];
#pragma unroll
        for (int t = 0; t < 5; t++) {
            int c = lane + t * 32;
            float e = (c < M_KV) ? expf(Sq[r * SS + c] - mx) : 0.f;
            ev[t] = e;
            sum += e;
        }
#pragma unroll
        for (int o = 16; o; o >>= 1) sum += __shfl_xor_sync(0xffffffffu, sum, o);
        float inv = 1.0f / sum;
#pragma unroll
        for (int t = 0; t < 5; t++) {
            int c = lane + t * 32;
            if (c < M_KV) Sq[r * SS + c] = tf32r(ev[t] * inv);
        }
    }
    __syncthreads();

    float acc2[4][4];
#pragma unroll
    for (int nt = 0; nt < 4; nt++)
#pragma unroll
        for (int r = 0; r < 4; r++) acc2[nt][r] = 0.f;

#pragma unroll
    for (int ks = 0; ks < 17; ks++) {
        const int kc = ks * 8 + tq;
        const int row = wm * 16 + quad;
        uint32_t a[4];
        a[0] = __float_as_uint(Sq[row * SS + kc]);
        a[1] = __float_as_uint(Sq[(row + 8) * SS + kc]);
        a[2] = __float_as_uint(Sq[row * SS + kc + 4]);
        a[3] = __float_as_uint(Sq[(row + 8) * SS + kc + 4]);
#pragma unroll
        for (int nt = 0; nt < 4; nt++) {
            int dr = wn * 32 + nt * 8 + quad;
            uint32_t bfr[2];
            bfr[0] = __float_as_uint(KV[dr * VS + kc]);
            bfr[1] = __float_as_uint(KV[dr * VS + kc + 4]);
            mma_tf32(acc2[nt], a, bfr);
        }
    }

    float o64 = 0.f;
    if (tid < HDIM) {
        for (int j = 0; j < M_KV; j++)
            o64 += Sq[64 * SS + j] * KV[tid * VS + j];
    }

#pragma unroll
    for (int nt = 0; nt < 4; nt++) {
        int i0 = wm * 16 + quad;
        int d0 = wn * 32 + nt * 8 + 2 * tq;
        float2 o0 = { acc2[nt][0], acc2[nt][1] };
        float2 o1 = { acc2[nt][2], acc2[nt][3] };
        *(float2*)&out[((size_t)(b * N_Q + i0)) * CDIM + h * HDIM + d0]     = o0;
        *(float2*)&out[((size_t)(b * N_Q + i0 + 8)) * CDIM + h * HDIM + d0] = o1;
    }
    if (tid < HDIM)
        out[((size_t)(b * N_Q + 64)) * CDIM + h * HDIM + tid] = o64;
}

// =======================================================================
// kernel_launch
// =======================================================================
extern "C" void kernel_launch(void* const* d_in, const int* in_sizes, int n_in,
                              void* d_out, int out_size)
{
    const float* x    = (const float*)d_in[0];
    const float* x_   = (const float*)d_in[1];
    const int*   mask_left  = (const int*)d_in[2];
    const int*   mask_right = (const int*)d_in[3];
    const int*   nW   = (const int*)d_in[4];
    const float* rel_table = (const float*)d_in[5];
    const float* cls_self  = (const float*)d_in[6];
    const float* cls_up    = (const float*)d_in[7];
    const float* cls_down  = (const float*)d_in[8];
    const float* Wq   = (const float*)d_in[9];
    const float* bq   = (const float*)d_in[10];
    const float* Wkv  = (const float*)d_in[11];
    const float* bkv  = (const float*)d_in[12];
    const float* Wp   = (const float*)d_in[13];
    const float* bp   = (const float*)d_in[14];
    float* out = (float*)d_out;

    const int Bq = in_sizes[0] / (N_Q * CDIM);   // 512

    float *qptr, *kvptr, *aptr;
    cudaGetSymbolAddress((void**)&qptr,  g_q);
    cudaGetSymbolAddress((void**)&kvptr, g_kv);
    cudaGetSymbolAddress((void**)&aptr,  g_att);

    cudaFuncSetAttribute(gemm_tf32_kernel,
                         cudaFuncAttributeMaxDynamicSharedMemorySize,
                         GEMM_SMEM_BYTES);
    cudaFuncSetAttribute(attn_kernel,
                         cudaFuncAttributeMaxDynamicSharedMemorySize,
                         ATTN_SMEM_BYTES);

    // 1) q = x @ Wq^T + bq : M = 33280, N = 512, K = 512
    {
        dim3 grid(CDIM / GBN, (Bq * N_Q) / GBM);        // (4, 260)
        gemm_tf32_kernel<<<grid, 256, GEMM_SMEM_BYTES>>>(x, Wq, bq, qptr, CDIM, CDIM);
    }
    // 2) kv = x_ @ Wkv^T + bkv : M = 66048, N = 1024, K = 512
    {
        dim3 grid((2 * CDIM) / GBN, (Bq * M_KV) / GBM); // (8, 516)
        gemm_tf32_kernel<<<grid, 256, GEMM_SMEM_BYTES>>>(x_, Wkv, bkv, kvptr, CDIM, 2 * CDIM);
    }
    // 3) fused tensorized attention -> g_att
    {
        attn_kernel<<<Bq * NH, 256, ATTN_SMEM_BYTES>>>(
            rel_table, cls_self, cls_up, cls_down,
            mask_left, mask_right, nW, aptr);
    }
    // 4) out = g_att @ Wp^T + bp : M = 33280, N = 512, K = 512
    {
        dim3 grid(CDIM / GBN, (Bq * N_Q) / GBM);
        gemm_tf32_kernel<<<grid, 256, GEMM_SMEM_BYTES>>>(aptr, Wp, bp, out, CDIM, CDIM);
    }
}

// round 10
// speedup vs baseline: 1.7395x; 1.6800x over previous
#include <cuda_runtime.h>
#include <cuda_fp16.h>
#include <math.h>
#include <float.h>
#include <stdint.h>

// ---------------- problem constants (fixed by dataset) ----------------
#define N_Q   65      // n = 1+W
#define M_KV  129     // m = 1+R
#define NH    8       // heads
#define HDIM  64      // head dim
#define CDIM  512     // model dim (= H*HD)
#define BQMAX 512     // B_ = 512

// ---------------- scratch (device globals; no allocation) -------------
__device__ __half h_x  [(size_t)BQMAX * N_Q  * CDIM];
__device__ __half h_x_ [(size_t)BQMAX * M_KV * CDIM];
__device__ __half h_wq [(size_t)CDIM * CDIM];
__device__ __half h_wkv[(size_t)2 * CDIM * CDIM];
__device__ __half h_wp [(size_t)CDIM * CDIM];
__device__ __half h_q  [(size_t)BQMAX * N_Q  * CDIM];
__device__ __half h_kv [(size_t)BQMAX * M_KV * 2 * CDIM];
__device__ __half h_att[(size_t)BQMAX * N_Q  * CDIM];

// ---------------- helpers ----------------------------------------------
__device__ __forceinline__ void mma_f16(float c[4], const uint32_t a[4],
                                        const uint32_t b[2]) {
    asm volatile(
        "mma.sync.aligned.m16n8k16.row.col.f32.f16.f16.f32 "
        "{%0,%1,%2,%3}, {%4,%5,%6,%7}, {%8,%9}, {%0,%1,%2,%3};"
        : "+f"(c[0]), "+f"(c[1]), "+f"(c[2]), "+f"(c[3])
        : "r"(a[0]), "r"(a[1]), "r"(a[2]), "r"(a[3]),
          "r"(b[0]), "r"(b[1]));
}
__device__ __forceinline__ void cp16(void* smem, const void* g) {
    uint32_t a = (uint32_t)__cvta_generic_to_shared(smem);
    asm volatile("cp.async.cg.shared.global [%0], [%1], 16;\n"
                 :: "r"(a), "l"(g));
}
__device__ __forceinline__ uint32_t h2u(__half2 h) {
    return *reinterpret_cast<uint32_t*>(&h);
}

// =======================================================================
// fp32 -> fp16 conversion pre-pass (8 elements / thread)
// =======================================================================
__global__ void cvt_fp16_kernel(const float* __restrict__ s,
                                __half* __restrict__ d, int n8)
{
    int i = blockIdx.x * blockDim.x + threadIdx.x;
    if (i >= n8) return;
    const float4 v0 = ((const float4*)s)[i * 2];
    const float4 v1 = ((const float4*)s)[i * 2 + 1];
    uint4 o;
    o.x = h2u(__floats2half2_rn(v0.x, v0.y));
    o.y = h2u(__floats2half2_rn(v0.z, v0.w));
    o.z = h2u(__floats2half2_rn(v1.x, v1.y));
    o.w = h2u(__floats2half2_rn(v1.z, v1.w));
    ((uint4*)d)[i] = o;
}

// =======================================================================
// FP16 tensor-core GEMM, cp.async 2-stage, SW128-swizzled smem.
//   C[M,N] = A[M,K] @ W[N,K]^T + bias[N]   (A, W fp16; accum/bias fp32)
// BM=128, BN=128, BK=64, 256 threads (8 warps = 2(M) x 4(N)),
// warp tile 64x32 (4x4 m16n8k16). Requires M%128==0, N%128==0, K%64==0.
// Smem tile row = 64 fp16 = 128 B, 16B segs XOR-swizzled by (row & 7).
// =======================================================================
#define GBM 128
#define GBN 128
#define GBK 64
#define TILE_B   (128 * 128)                  // 16384 bytes per operand tile
#define STAGE_B  (2 * TILE_B)                 // A + B per stage
#define GEMM_SMEM_BYTES (2 * STAGE_B)         // 65536

__global__ __launch_bounds__(256, 2) void gemm_f16_kernel(
    const __half* __restrict__ A, const __half* __restrict__ W,
    const float* __restrict__ bias, void* __restrict__ Cv,
    int K, int N, int outHalf)
{
    extern __shared__ char smem[];

    const int tid    = threadIdx.x;
    const int warp   = tid >> 5;
    const int lane   = tid & 31;
    const int quad   = lane >> 2;
    const int tq     = lane & 3;
    const int warp_m = warp >> 2;          // 0..1 (64 rows)
    const int warp_n = warp & 3;           // 0..3 (32 cols)
    const int rowBase = blockIdx.y * GBM;
    const int colBase = blockIdx.x * GBN;

    const __half* Ap = A + (size_t)rowBase * K;
    const __half* Wp = W + (size_t)colBase * K;

    float acc[4][4][4];
#pragma unroll
    for (int mt = 0; mt < 4; mt++)
#pragma unroll
        for (int nt = 0; nt < 4; nt++)
#pragma unroll
            for (int r = 0; r < 4; r++) acc[mt][nt][r] = 0.f;

    const int NITER = K >> 6;              // BK = 64

    // cp.async producer: 4 A-chunks + 4 B-chunks of 16B per thread
    auto issue = [&](int it) {
        char* aS = smem + (it & 1) * STAGE_B;
        char* bS = aS + TILE_B;
        const int k0 = it * GBK;
#pragma unroll
        for (int i = 0; i < 4; i++) {
            int f   = tid + i * 256;
            int r   = f >> 3;
            int seg = f & 7;
            int dst = r * 128 + ((seg ^ (r & 7)) * 16);
            cp16(aS + dst, Ap + (size_t)r * K + k0 + seg * 8);
            cp16(bS + dst, Wp + (size_t)r * K + k0 + seg * 8);
        }
    };

    issue(0);
    asm volatile("cp.async.commit_group;\n");

    for (int it = 0; it < NITER; it++) {
        if (it + 1 < NITER) {
            issue(it + 1);
            asm volatile("cp.async.commit_group;\n");
            asm volatile("cp.async.wait_group 1;\n");
        } else {
            asm volatile("cp.async.wait_group 0;\n");
        }
        __syncthreads();

        const char* aS = smem + (it & 1) * STAGE_B;
        const char* bS = aS + TILE_B;

#pragma unroll
        for (int ks = 0; ks < 4; ks++) {   // 4 x k16 per BK=64
            const int segL = ((2 * ks)     ^ quad) * 16 + tq * 4;
            const int segH = ((2 * ks + 1) ^ quad) * 16 + tq * 4;
            uint32_t af[4][4];
            uint32_t bf[4][2];
#pragma unroll
            for (int mt = 0; mt < 4; mt++) {
                int r = warp_m * 64 + mt * 16 + quad;
                af[mt][0] = *(const uint32_t*)(aS + r * 128 + segL);
                af[mt][1] = *(const uint32_t*)(aS + (r + 8) * 128 + segL);
                af[mt][2] = *(const uint32_t*)(aS + r * 128 + segH);
                af[mt][3] = *(const uint32_t*)(aS + (r + 8) * 128 + segH);
            }
#pragma unroll
            for (int nt = 0; nt < 4; nt++) {
                int r = warp_n * 32 + nt * 8 + quad;
                bf[nt][0] = *(const uint32_t*)(bS + r * 128 + segL);
                bf[nt][1] = *(const uint32_t*)(bS + r * 128 + segH);
            }
#pragma unroll
            for (int mt = 0; mt < 4; mt++)
#pragma unroll
                for (int nt = 0; nt < 4; nt++)
                    mma_f16(acc[mt][nt], af[mt], bf[nt]);
        }
        __syncthreads();
    }

    // ---- epilogue: bias + store (fp16 intermediates or fp32 final)
#pragma unroll
    for (int mt = 0; mt < 4; mt++) {
        int r0 = rowBase + warp_m * 64 + mt * 16 + quad;
#pragma unroll
        for (int nt = 0; nt < 4; nt++) {
            int c = colBase + warp_n * 32 + nt * 8 + 2 * tq;
            float2 bv = *(const float2*)&bias[c];
            float ox0 = acc[mt][nt][0] + bv.x;
            float oy0 = acc[mt][nt][1] + bv.y;
            float ox1 = acc[mt][nt][2] + bv.x;
            float oy1 = acc[mt][nt][3] + bv.y;
            if (outHalf) {
                __half* Ch = (__half*)Cv;
                *(uint32_t*)&Ch[(size_t)r0 * N + c] =
                    h2u(__floats2half2_rn(ox0, oy0));
                *(uint32_t*)&Ch[(size_t)(r0 + 8) * N + c] =
                    h2u(__floats2half2_rn(ox1, oy1));
            } else {
                float* Cf = (float*)Cv;
                *(float2*)&Cf[(size_t)r0 * N + c]       = make_float2(ox0, oy0);
                *(float2*)&Cf[(size_t)(r0 + 8) * N + c] = make_float2(ox1, oy1);
            }
        }
    }
}

// =======================================================================
// FP16 fused window attention: one block per (b, h), 256 threads.
// QK^T and PV via m16n8k16 fp16 (rows 0..63); row 64 scalar.
// Softmax/bias/mask in fp32.  Word-region layout:
//   R1 [0, 4940):        q fp16 [65][72h] -> P fp16 [65][152h] (overlay)
//   R2 [4940, 10124):    k fp16 [144][72h] -> v^T fp16 [64][152h] (overlay)
//   S  [10124, 18704):   S fp32 [65][132]
//   tables [18704, 19088)
// =======================================================================
#define QKH 72        // q/k row stride (halves); 36 words, 36%8==4 -> ok
#define PVH 152       // P/vT row stride (halves); 76 words, 76%8==4 -> ok
#define SSW 132       // S fp32 row stride (words)
#define R1_W   4940
#define R2_W   5184
#define OFF_S  (R1_W + R2_W)
#define OFF_BR (OFF_S + N_Q * SSW)
#define OFF_BU (OFF_BR + 191)
#define OFF_BD (OFF_BU + 128)
#define OFF_BSF (OFF_BD + 64)
#define ATTN_W (OFF_BSF + 1)
#define ATTN_SMEM_BYTES (ATTN_W * 4)

__global__ __launch_bounds__(256, 2) void attn_kernel(
    const float* __restrict__ rel_table,
    const float* __restrict__ cls_self,
    const float* __restrict__ cls_up,
    const float* __restrict__ cls_down,
    const int*   __restrict__ mask_left,
    const int*   __restrict__ mask_right,
    const int*   __restrict__ nW_ptr,
    __half* __restrict__ out)
{
    extern __shared__ float sm[];
    __half* qh  = (__half*)sm;                 // then P (overlay)
    __half* ph  = (__half*)sm;
    __half* kh  = (__half*)(sm + R1_W);        // then v^T (overlay)
    __half* vh  = (__half*)(sm + R1_W);
    float*  S   = sm + OFF_S;
    float*  brl = sm + OFF_BR;
    float*  bup = sm + OFF_BU;
    float*  bdn = sm + OFF_BD;
    float*  bsf = sm + OFF_BSF;

    const int bid  = blockIdx.x;
    const int b    = bid >> 3;
    const int h    = bid & 7;
    const int tid  = threadIdx.x;
    const int warp = tid >> 5;
    const int lane = tid & 31;
    const int quad = lane >> 2;
    const int tq   = lane & 3;
    const int wm   = warp >> 1;     // 0..3 : 16-row group
    const int wn   = warp & 1;      // 0..1
    const int nW   = *nW_ptr;

    // ---- bias tables
    if (tid < 191) brl[tid] = rel_table[tid * NH + h];
    if (tid < 128) bup[tid] = cls_up[h * 128 + tid];
    if (tid < 64)  bdn[tid] = cls_down[h * 64 + tid];
    if (tid == 224) bsf[0]  = cls_self[h];

    // ---- load q fp16 (65 x 64h), row stride 72h (16B-aligned chunks)
    for (int idx = tid; idx < N_Q * 8; idx += 256) {
        int i = idx >> 3, c = idx & 7;
        uint4 v = *(const uint4*)&h_q[((size_t)(b * N_Q + i)) * CDIM + h * HDIM + c * 8];
        *(uint4*)&qh[i * QKH + c * 8] = v;
    }
    // ---- load k fp16 (129 x 64h), zero rows 129..143
    for (int idx = tid; idx < 144 * 8; idx += 256) {
        int j = idx >> 3, c = idx & 7;
        uint4 v = {0u, 0u, 0u, 0u};
        if (j < M_KV)
            v = *(const uint4*)&h_kv[((size_t)(b * M_KV + j)) * (2 * CDIM)
                                     + h * HDIM + c * 8];
        *(uint4*)&kh[j * QKH + c * 8] = v;
    }
    __syncthreads();

    // ---- QK^T: rows 0..63, 9 n-tiles per warp half (j up to 143)
    const int nbase = wn * 72;
    float acc[9][4];
#pragma unroll
    for (int nt = 0; nt < 9; nt++)
#pragma unroll
        for (int r = 0; r < 4; r++) acc[nt][r] = 0.f;

    const uint32_t* qw = (const uint32_t*)qh;
    const uint32_t* kw = (const uint32_t*)kh;
#pragma unroll
    for (int ks = 0; ks < 4; ks++) {       // K = 64 -> 4 x k16
        const int wl = ks * 8 + tq;
        const int row = wm * 16 + quad;
        uint32_t a[4];
        a[0] = qw[row * 36 + wl];
        a[1] = qw[(row + 8) * 36 + wl];
        a[2] = qw[row * 36 + wl + 4];
        a[3] = qw[(row + 8) * 36 + wl + 4];
#pragma unroll
        for (int nt = 0; nt < 9; nt++) {
            int jr = nbase + nt * 8 + quad;
            uint32_t bfr[2];
            bfr[0] = kw[jr * 36 + wl];
            bfr[1] = kw[jr * 36 + wl + 4];
            mma_f16(acc[nt], a, bfr);
        }
    }

    // ---- row 64 scalar logits
    float s64 = 0.f;
    if (tid < M_KV) {
#pragma unroll 8
        for (int d = 0; d < HDIM; d++)
            s64 += __half2float(qh[64 * QKH + d]) * __half2float(kh[tid * QKH + d]);
    }
    __syncthreads();   // q & k fully consumed

    // ---- masks
    const int mc   = (nW < 4) ? nW : 4;
    const int w    = b % nW;
    const bool hasL = (w < mc);
    const bool hasR = (w >= nW - mc);
    const int* mlp = mask_left  + (size_t)w * N_Q * M_KV;
    const int* mrp = mask_right + (size_t)(w - nW + 4) * N_Q * M_KV;

    // ---- S = scale*acc + bias, masked (rows 0..63, fp32)
#pragma unroll
    for (int nt = 0; nt < 9; nt++) {
        int j0 = nbase + nt * 8 + 2 * tq;
        int i0 = wm * 16 + quad;
#pragma unroll
        for (int e = 0; e < 4; e++) {
            int i = i0 + (e >> 1) * 8;
            int j = j0 + (e & 1);
            if (j >= M_KV) continue;
            float bias;
            if (i == 0)      bias = (j == 0) ? bsf[0] : bup[j - 1];
            else if (j == 0) bias = bdn[i - 1];
            else             bias = brl[i - j + 127];
            float s = acc[nt][e] * 0.125f + bias;
            if (hasL && mlp[i * M_KV + j] == 1) s = -FLT_MAX;
            if (hasR && mrp[i * M_KV + j] == 1) s = -FLT_MAX;
            S[i * SSW + j] = s;
        }
    }
    if (tid < M_KV) {
        int j = tid;
        float bias = (j == 0) ? bdn[63] : brl[64 - j + 127];
        float s = s64 * 0.125f + bias;
        if (hasL && mlp[64 * M_KV + j] == 1) s = -FLT_MAX;
        if (hasR && mrp[64 * M_KV + j] == 1) s = -FLT_MAX;
        S[64 * SSW + j] = s;
    }

    // ---- zero P pad cols 129..143 (PV iterates k to 143)
    for (int idx = tid; idx < N_Q * 15; idx += 256) {
        int i = idx / 15, c = M_KV + idx % 15;
        ph[i * PVH + c] = __float2half(0.f);
    }
    // ---- load v transposed: vh[d][j], zero j 129..143
    for (int idx = tid; idx < 144 * HDIM; idx += 256) {
        int j = idx >> 6, d = idx & 63;
        __half v = __float2half(0.f);
        if (j < M_KV)
            v = h_kv[((size_t)(b * M_KV + j)) * (2 * CDIM) + CDIM + h * HDIM + d];
        vh[d * PVH + j] = v;
    }
    __syncthreads();

    // ---- softmax rows 0..64 over fp32 S; write fp16 P
    for (int r = warp; r < N_Q; r += 8) {
        float mx = -FLT_MAX;
        for (int c = lane; c < M_KV; c += 32) mx = fmaxf(mx, S[r * SSW + c]);
#pragma unroll
        for (int o = 16; o; o >>= 1) mx = fmaxf(mx, __shfl_xor_sync(0xffffffffu, mx, o));
        float sum = 0.f;
        float ev[5];
#pragma unroll
        for (int t = 0; t < 5; t++) {
            int c = lane + t * 32;
            float e = (c < M_KV) ? expf(S[r * SSW + c] - mx) : 0.f;
            ev[t] = e;
            sum += e;
        }
#pragma unroll
        for (int o = 16; o; o >>= 1) sum += __shfl_xor_sync(0xffffffffu, sum, o);
        float inv = 1.0f / sum;
#pragma unroll
        for (int t = 0; t < 5; t++) {
            int c = lane + t * 32;
            if (c < M_KV) ph[r * PVH + c] = __float2half_rn(ev[t] * inv);
        }
    }
    __syncthreads();

    // ---- PV: O[i][d] = sum_j P[i][j] v[j][d]; K = 144 -> 9 x k16
    float acc2[4][4];
#pragma unroll
    for (int nt = 0; nt < 4; nt++)
#pragma unroll
        for (int r = 0; r < 4; r++) acc2[nt][r] = 0.f;

    const uint32_t* pw = (const uint32_t*)ph;
    const uint32_t* vw = (const uint32_t*)vh;
#pragma unroll
    for (int ks = 0; ks < 9; ks++) {
        const int wl = ks * 8 + tq;
        const int row = wm * 16 + quad;
        uint32_t a[4];
        a[0] = pw[row * 76 + wl];
        a[1] = pw[(row + 8) * 76 + wl];
        a[2] = pw[row * 76 + wl + 4];
        a[3] = pw[(row + 8) * 76 + wl + 4];
#pragma unroll
        for (int nt = 0; nt < 4; nt++) {
            int dr = wn * 32 + nt * 8 + quad;
            uint32_t bfr[2];
            bfr[0] = vw[dr * 76 + wl];
            bfr[1] = vw[dr * 76 + wl + 4];
            mma_f16(acc2[nt], a, bfr);
        }
    }

    // ---- row 64 scalar PV
    float o64 = 0.f;
    if (tid < HDIM) {
        for (int j = 0; j < M_KV; j++)
            o64 += __half2float(ph[64 * PVH + j]) * __half2float(vh[tid * PVH + j]);
    }

    // ---- write output (fp16) rows 0..63
#pragma unroll
    for (int nt = 0; nt < 4; nt++) {
        int i0 = wm * 16 + quad;
        int d0 = wn * 32 + nt * 8 + 2 * tq;
        *(uint32_t*)&out[((size_t)(b * N_Q + i0)) * CDIM + h * HDIM + d0] =
            h2u(__floats2half2_rn(acc2[nt][0], acc2[nt][1]));
        *(uint32_t*)&out[((size_t)(b * N_Q + i0 + 8)) * CDIM + h * HDIM + d0] =
            h2u(__floats2half2_rn(acc2[nt][2], acc2[nt][3]));
    }
    if (tid < HDIM)
        out[((size_t)(b * N_Q + 64)) * CDIM + h * HDIM + tid] = __float2half_rn(o64);
}

// =======================================================================
// kernel_launch
// =======================================================================
extern "C" void kernel_launch(void* const* d_in, const int* in_sizes, int n_in,
                              void* d_out, int out_size)
{
    const float* x    = (const float*)d_in[0];
    const float* x_   = (const float*)d_in[1];
    const int*   mask_left  = (const int*)d_in[2];
    const int*   mask_right = (const int*)d_in[3];
    const int*   nW   = (const int*)d_in[4];
    const float* rel_table = (const float*)d_in[5];
    const float* cls_self  = (const float*)d_in[6];
    const float* cls_up    = (const float*)d_in[7];
    const float* cls_down  = (const float*)d_in[8];
    const float* Wq   = (const float*)d_in[9];
    const float* bq   = (const float*)d_in[10];
    const float* Wkv  = (const float*)d_in[11];
    const float* bkv  = (const float*)d_in[12];
    const float* Wp   = (const float*)d_in[13];
    const float* bp   = (const float*)d_in[14];
    float* out = (float*)d_out;

    const int Bq = in_sizes[0] / (N_Q * CDIM);   // 512

    __half *hx, *hx_, *hwq, *hwkv, *hwp, *hq, *hkv, *hatt;
    cudaGetSymbolAddress((void**)&hx,   h_x);
    cudaGetSymbolAddress((void**)&hx_,  h_x_);
    cudaGetSymbolAddress((void**)&hwq,  h_wq);
    cudaGetSymbolAddress((void**)&hwkv, h_wkv);
    cudaGetSymbolAddress((void**)&hwp,  h_wp);
    cudaGetSymbolAddress((void**)&hq,   h_q);
    cudaGetSymbolAddress((void**)&hkv,  h_kv);
    cudaGetSymbolAddress((void**)&hatt, h_att);

    cudaFuncSetAttribute(gemm_f16_kernel,
                         cudaFuncAttributeMaxDynamicSharedMemorySize,
                         GEMM_SMEM_BYTES);
    cudaFuncSetAttribute(attn_kernel,
                         cudaFuncAttributeMaxDynamicSharedMemorySize,
                         ATTN_SMEM_BYTES);

    // 0) fp32 -> fp16 pre-pass
    {
        int n;
        n = Bq * N_Q * CDIM / 8;
        cvt_fp16_kernel<<<(n + 255) / 256, 256>>>(x, hx, n);
        n = Bq * M_KV * CDIM / 8;
        cvt_fp16_kernel<<<(n + 255) / 256, 256>>>(x_, hx_, n);
        n = CDIM * CDIM / 8;
        cvt_fp16_kernel<<<(n + 255) / 256, 256>>>(Wq, hwq, n);
        n = 2 * CDIM * CDIM / 8;
        cvt_fp16_kernel<<<(n + 255) / 256, 256>>>(Wkv, hwkv, n);
        n = CDIM * CDIM / 8;
        cvt_fp16_kernel<<<(n + 255) / 256, 256>>>(Wp, hwp, n);
    }

    // 1) q = x @ Wq^T + bq : M = 33280, N = 512, K = 512   -> fp16
    {
        dim3 grid(CDIM / GBN, (Bq * N_Q) / GBM);
        gemm_f16_kernel<<<grid, 256, GEMM_SMEM_BYTES>>>(
            hx, hwq, bq, hq, CDIM, CDIM, 1);
    }
    // 2) kv = x_ @ Wkv^T + bkv : M = 66048, N = 1024, K = 512 -> fp16
    {
        dim3 grid((2 * CDIM) / GBN, (Bq * M_KV) / GBM);
        gemm_f16_kernel<<<grid, 256, GEMM_SMEM_BYTES>>>(
            hx_, hwkv, bkv, hkv, CDIM, 2 * CDIM, 1);
    }
    // 3) fused fp16 attention -> h_att
    {
        attn_kernel<<<Bq * NH, 256, ATTN_SMEM_BYTES>>>(
            rel_table, cls_self, cls_up, cls_down,
            mask_left, mask_right, nW, hatt);
    }
    // 4) out = att @ Wp^T + bp : M = 33280, N = 512, K = 512 -> fp32
    {
        dim3 grid(CDIM / GBN, (Bq * N_Q) / GBM);
        gemm_f16_kernel<<<grid, 256, GEMM_SMEM_BYTES>>>(
            hatt, hwp, bp, out, CDIM, CDIM, 0);
    }
}

// round 11
// speedup vs baseline: 1.7615x; 1.0127x over previous
#include <cuda_runtime.h>
#include <cuda_fp16.h>
#include <math.h>
#include <float.h>
#include <stdint.h>

// ---------------- problem constants (fixed by dataset) ----------------
#define N_Q   65      // n = 1+W
#define M_KV  129     // m = 1+R
#define NH    8       // heads
#define HDIM  64      // head dim
#define CDIM  512     // model dim (= H*HD)
#define BQMAX 512     // B_ = 512

// ---------------- scratch (device globals; no allocation) -------------
__device__ __half h_x  [(size_t)BQMAX * N_Q  * CDIM];
__device__ __half h_x_ [(size_t)BQMAX * M_KV * CDIM];
__device__ __half h_wq [(size_t)CDIM * CDIM];
__device__ __half h_wkv[(size_t)2 * CDIM * CDIM];
__device__ __half h_wp [(size_t)CDIM * CDIM];
__device__ __half h_q  [(size_t)BQMAX * N_Q  * CDIM];
__device__ __half h_kv [(size_t)BQMAX * M_KV * 2 * CDIM];
__device__ __half h_att[(size_t)BQMAX * N_Q  * CDIM];

// ---------------- helpers ----------------------------------------------
__device__ __forceinline__ void mma_f16(float c[4], const uint32_t a[4],
                                        const uint32_t b[2]) {
    asm volatile(
        "mma.sync.aligned.m16n8k16.row.col.f32.f16.f16.f32 "
        "{%0,%1,%2,%3}, {%4,%5,%6,%7}, {%8,%9}, {%0,%1,%2,%3};"
        : "+f"(c[0]), "+f"(c[1]), "+f"(c[2]), "+f"(c[3])
        : "r"(a[0]), "r"(a[1]), "r"(a[2]), "r"(a[3]),
          "r"(b[0]), "r"(b[1]));
}
__device__ __forceinline__ void cp16(void* smem, const void* g) {
    uint32_t a = (uint32_t)__cvta_generic_to_shared(smem);
    asm volatile("cp.async.cg.shared.global [%0], [%1], 16;\n"
                 :: "r"(a), "l"(g));
}
__device__ __forceinline__ uint32_t h2u(__half2 h) {
    return *reinterpret_cast<uint32_t*>(&h);
}
__device__ __forceinline__ uint32_t s2u(const void* p) {
    return (uint32_t)__cvta_generic_to_shared(p);
}
__device__ __forceinline__ void ldsm_x4(uint32_t r[4], uint32_t addr) {
    asm volatile("ldmatrix.sync.aligned.m8n8.x4.shared.b16 {%0,%1,%2,%3}, [%4];"
                 : "=r"(r[0]), "=r"(r[1]), "=r"(r[2]), "=r"(r[3]) : "r"(addr));
}
__device__ __forceinline__ void ldsm_x2(uint32_t r[2], uint32_t addr) {
    asm volatile("ldmatrix.sync.aligned.m8n8.x2.shared.b16 {%0,%1}, [%2];"
                 : "=r"(r[0]), "=r"(r[1]) : "r"(addr));
}

// =======================================================================
// fp32 -> fp16 conversion pre-pass (8 elements / thread)
// =======================================================================
__global__ void cvt_fp16_kernel(const float* __restrict__ s,
                                __half* __restrict__ d, int n8)
{
    int i = blockIdx.x * blockDim.x + threadIdx.x;
    if (i >= n8) return;
    const float4 v0 = ((const float4*)s)[i * 2];
    const float4 v1 = ((const float4*)s)[i * 2 + 1];
    uint4 o;
    o.x = h2u(__floats2half2_rn(v0.x, v0.y));
    o.y = h2u(__floats2half2_rn(v0.z, v0.w));
    o.z = h2u(__floats2half2_rn(v1.x, v1.y));
    o.w = h2u(__floats2half2_rn(v1.z, v1.w));
    ((uint4*)d)[i] = o;
}

// =======================================================================
// FP16 tensor-core GEMM, cp.async 2-stage, SW128-swizzled smem, ldmatrix.
//   C[M,N] = A[M,K] @ W[N,K]^T + bias[N]   (A, W fp16; accum/bias fp32)
// BM=128, BN=128, BK=64, 256 threads (8 warps = 2(M) x 4(N)),
// warp tile 64x32 (4x4 m16n8k16). Requires M%128==0, N%128==0, K%64==0.
// =======================================================================
#define GBM 128
#define GBN 128
#define GBK 64
#define TILE_B   (128 * 128)                  // 16384 bytes per operand tile
#define STAGE_B  (2 * TILE_B)                 // A + B per stage
#define GEMM_SMEM_BYTES (2 * STAGE_B)         // 65536

__global__ __launch_bounds__(256, 2) void gemm_f16_kernel(
    const __half* __restrict__ A, const __half* __restrict__ W,
    const float* __restrict__ bias, void* __restrict__ Cv,
    int K, int N, int outHalf)
{
    extern __shared__ char smem[];

    const int tid    = threadIdx.x;
    const int warp   = tid >> 5;
    const int lane   = tid & 31;
    const int quad   = lane >> 2;
    const int tq     = lane & 3;
    const int lo7    = lane & 7;
    const int l3     = (lane >> 3) & 1;
    const int hi     = lane >> 4;
    const int warp_m = warp >> 2;          // 0..1 (64 rows)
    const int warp_n = warp & 3;           // 0..3 (32 cols)
    const int rowBase = blockIdx.y * GBM;
    const int colBase = blockIdx.x * GBN;

    const __half* Ap = A + (size_t)rowBase * K;
    const __half* Wp = W + (size_t)colBase * K;

    float acc[4][4][4];
#pragma unroll
    for (int mt = 0; mt < 4; mt++)
#pragma unroll
        for (int nt = 0; nt < 4; nt++)
#pragma unroll
            for (int r = 0; r < 4; r++) acc[mt][nt][r] = 0.f;

    const uint32_t sbase = s2u(smem);
    // per-lane constant components of ldmatrix addresses
    const uint32_t aRow = (uint32_t)((warp_m * 64 + lo7 + 8 * l3) * 128);
    const uint32_t bRow = (uint32_t)((warp_n * 32 + lo7) * 128);

    const int NITER = K >> 6;              // BK = 64

    auto issue = [&](int it) {
        char* aS = smem + (it & 1) * STAGE_B;
        char* bS = aS + TILE_B;
        const int k0 = it * GBK;
#pragma unroll
        for (int i = 0; i < 4; i++) {
            int f   = tid + i * 256;
            int r   = f >> 3;
            int seg = f & 7;
            int dst = r * 128 + ((seg ^ (r & 7)) * 16);
            cp16(aS + dst, Ap + (size_t)r * K + k0 + seg * 8);
            cp16(bS + dst, Wp + (size_t)r * K + k0 + seg * 8);
        }
    };

    issue(0);
    asm volatile("cp.async.commit_group;\n");

    for (int it = 0; it < NITER; it++) {
        if (it + 1 < NITER) {
            issue(it + 1);
            asm volatile("cp.async.commit_group;\n");
            asm volatile("cp.async.wait_group 1;\n");
        } else {
            asm volatile("cp.async.wait_group 0;\n");
        }
        __syncthreads();

        const uint32_t aBase = sbase + (it & 1) * STAGE_B;
        const uint32_t bBase = aBase + TILE_B;

#pragma unroll
        for (int ks = 0; ks < 4; ks++) {
            // swizzled 16B-seg offsets for this lane, this k16 step
            const uint32_t aSeg = (uint32_t)(((2 * ks + hi) ^ lo7) * 16);
            const uint32_t bSeg = (uint32_t)(((2 * ks + l3) ^ lo7) * 16);
            uint32_t af[4][4];
            uint32_t bf[4][2];
#pragma unroll
            for (int mt = 0; mt < 4; mt++)
                ldsm_x4(af[mt], aBase + aRow + (uint32_t)(mt * 16 * 128) + aSeg);
#pragma unroll
            for (int nt = 0; nt < 4; nt++)
                ldsm_x2(bf[nt], bBase + bRow + (uint32_t)(nt * 8 * 128) + bSeg);
#pragma unroll
            for (int mt = 0; mt < 4; mt++)
#pragma unroll
                for (int nt = 0; nt < 4; nt++)
                    mma_f16(acc[mt][nt], af[mt], bf[nt]);
        }
        __syncthreads();
    }

    // ---- epilogue: bias + store (fp16 intermediates or fp32 final)
#pragma unroll
    for (int mt = 0; mt < 4; mt++) {
        int r0 = rowBase + warp_m * 64 + mt * 16 + quad;
#pragma unroll
        for (int nt = 0; nt < 4; nt++) {
            int c = colBase + warp_n * 32 + nt * 8 + 2 * tq;
            float2 bv = *(const float2*)&bias[c];
            float ox0 = acc[mt][nt][0] + bv.x;
            float oy0 = acc[mt][nt][1] + bv.y;
            float ox1 = acc[mt][nt][2] + bv.x;
            float oy1 = acc[mt][nt][3] + bv.y;
            if (outHalf) {
                __half* Ch = (__half*)Cv;
                *(uint32_t*)&Ch[(size_t)r0 * N + c] =
                    h2u(__floats2half2_rn(ox0, oy0));
                *(uint32_t*)&Ch[(size_t)(r0 + 8) * N + c] =
                    h2u(__floats2half2_rn(ox1, oy1));
            } else {
                float* Cf = (float*)Cv;
                *(float2*)&Cf[(size_t)r0 * N + c]       = make_float2(ox0, oy0);
                *(float2*)&Cf[(size_t)(r0 + 8) * N + c] = make_float2(ox1, oy1);
            }
        }
    }
}

// =======================================================================
// FP16 fused window attention with ldmatrix fragments.
// Layout identical to R10 (word regions):
//   R1 [0, 4940):      q fp16 [65][72h] -> P fp16 [65][152h] (overlay)
//   R2 [4940, 10124):  k fp16 [144][72h] -> v^T fp16 [64][152h] (overlay)
//   S  [10124, 18704): S fp32 [65][132]
//   tables [18704, 19088)
// =======================================================================
#define QKH 72        // q/k row stride (halves) = 144 B
#define PVH 152       // P/vT row stride (halves) = 304 B
#define SSW 132
#define R1_W   4940
#define R2_W   5184
#define OFF_S  (R1_W + R2_W)
#define OFF_BR (OFF_S + N_Q * SSW)
#define OFF_BU (OFF_BR + 191)
#define OFF_BD (OFF_BU + 128)
#define OFF_BSF (OFF_BD + 64)
#define ATTN_W (OFF_BSF + 1)
#define ATTN_SMEM_BYTES (ATTN_W * 4)

__global__ __launch_bounds__(256, 2) void attn_kernel(
    const float* __restrict__ rel_table,
    const float* __restrict__ cls_self,
    const float* __restrict__ cls_up,
    const float* __restrict__ cls_down,
    const int*   __restrict__ mask_left,
    const int*   __restrict__ mask_right,
    const int*   __restrict__ nW_ptr,
    __half* __restrict__ out)
{
    extern __shared__ float sm[];
    __half* qh  = (__half*)sm;
    __half* ph  = (__half*)sm;
    __half* kh  = (__half*)(sm + R1_W);
    __half* vh  = (__half*)(sm + R1_W);
    float*  S   = sm + OFF_S;
    float*  brl = sm + OFF_BR;
    float*  bup = sm + OFF_BU;
    float*  bdn = sm + OFF_BD;
    float*  bsf = sm + OFF_BSF;

    const int bid  = blockIdx.x;
    const int b    = bid >> 3;
    const int h    = bid & 7;
    const int tid  = threadIdx.x;
    const int warp = tid >> 5;
    const int lane = tid & 31;
    const int quad = lane >> 2;
    const int tq   = lane & 3;
    const int lo7  = lane & 7;
    const int l3   = (lane >> 3) & 1;
    const int hi   = lane >> 4;
    const int wm   = warp >> 1;     // 0..3 : 16-row group
    const int wn   = warp & 1;      // 0..1
    const int nW   = *nW_ptr;

    // ---- bias tables
    if (tid < 191) brl[tid] = rel_table[tid * NH + h];
    if (tid < 128) bup[tid] = cls_up[h * 128 + tid];
    if (tid < 64)  bdn[tid] = cls_down[h * 64 + tid];
    if (tid == 224) bsf[0]  = cls_self[h];

    // ---- load q fp16 (65 x 64h)
    for (int idx = tid; idx < N_Q * 8; idx += 256) {
        int i = idx >> 3, c = idx & 7;
        uint4 v = *(const uint4*)&h_q[((size_t)(b * N_Q + i)) * CDIM + h * HDIM + c * 8];
        *(uint4*)&qh[i * QKH + c * 8] = v;
    }
    // ---- load k fp16 (129 x 64h), zero rows 129..143
    for (int idx = tid; idx < 144 * 8; idx += 256) {
        int j = idx >> 3, c = idx & 7;
        uint4 v = {0u, 0u, 0u, 0u};
        if (j < M_KV)
            v = *(const uint4*)&h_kv[((size_t)(b * M_KV + j)) * (2 * CDIM)
                                     + h * HDIM + c * 8];
        *(uint4*)&kh[j * QKH + c * 8] = v;
    }
    __syncthreads();

    // ---- QK^T: rows 0..63, 9 n-tiles per warp half (j up to 143)
    const int nbase = wn * 72;
    float acc[9][4];
#pragma unroll
    for (int nt = 0; nt < 9; nt++)
#pragma unroll
        for (int r = 0; r < 4; r++) acc[nt][r] = 0.f;

    {
        const uint32_t qB = s2u(qh) + (uint32_t)((wm * 16 + lo7 + 8 * l3) * 144);
        const uint32_t kB = s2u(kh) + (uint32_t)((nbase + lo7) * 144);
#pragma unroll
        for (int ks = 0; ks < 4; ks++) {       // K = 64 -> 4 x k16
            uint32_t a[4];
            ldsm_x4(a, qB + (uint32_t)(ks * 32 + 16 * hi));
#pragma unroll
            for (int nt = 0; nt < 9; nt++) {
                uint32_t bfr[2];
                ldsm_x2(bfr, kB + (uint32_t)(nt * 8 * 144 + ks * 32 + 16 * l3));
                mma_f16(acc[nt], a, bfr);
            }
        }
    }

    // ---- row 64 scalar logits
    float s64 = 0.f;
    if (tid < M_KV) {
#pragma unroll 8
        for (int d = 0; d < HDIM; d++)
            s64 += __half2float(qh[64 * QKH + d]) * __half2float(kh[tid * QKH + d]);
    }
    __syncthreads();   // q & k fully consumed

    // ---- masks
    const int mc   = (nW < 4) ? nW : 4;
    const int w    = b % nW;
    const bool hasL = (w < mc);
    const bool hasR = (w >= nW - mc);
    const int* mlp = mask_left  + (size_t)w * N_Q * M_KV;
    const int* mrp = mask_right + (size_t)(w - nW + 4) * N_Q * M_KV;

    // ---- S = scale*acc + bias, masked (rows 0..63, fp32)
#pragma unroll
    for (int nt = 0; nt < 9; nt++) {
        int j0 = nbase + nt * 8 + 2 * tq;
        int i0 = wm * 16 + quad;
#pragma unroll
        for (int e = 0; e < 4; e++) {
            int i = i0 + (e >> 1) * 8;
            int j = j0 + (e & 1);
            if (j >= M_KV) continue;
            float bias;
            if (i == 0)      bias = (j == 0) ? bsf[0] : bup[j - 1];
            else if (j == 0) bias = bdn[i - 1];
            else             bias = brl[i - j + 127];
            float s = acc[nt][e] * 0.125f + bias;
            if (hasL && mlp[i * M_KV + j] == 1) s = -FLT_MAX;
            if (hasR && mrp[i * M_KV + j] == 1) s = -FLT_MAX;
            S[i * SSW + j] = s;
        }
    }
    if (tid < M_KV) {
        int j = tid;
        float bias = (j == 0) ? bdn[63] : brl[64 - j + 127];
        float s = s64 * 0.125f + bias;
        if (hasL && mlp[64 * M_KV + j] == 1) s = -FLT_MAX;
        if (hasR && mrp[64 * M_KV + j] == 1) s = -FLT_MAX;
        S[64 * SSW + j] = s;
    }

    // ---- zero P pad cols 129..143
    for (int idx = tid; idx < N_Q * 15; idx += 256) {
        int i = idx / 15, c = M_KV + idx % 15;
        ph[i * PVH + c] = __float2half(0.f);
    }
    // ---- load v transposed: vh[d][j], zero j 129..143
    for (int idx = tid; idx < 144 * HDIM; idx += 256) {
        int j = idx >> 6, d = idx & 63;
        __half v = __float2half(0.f);
        if (j < M_KV)
            v = h_kv[((size_t)(b * M_KV + j)) * (2 * CDIM) + CDIM + h * HDIM + d];
        vh[d * PVH + j] = v;
    }
    __syncthreads();

    // ---- softmax rows 0..64 over fp32 S; write fp16 P
    for (int r = warp; r < N_Q; r += 8) {
        float mx = -FLT_MAX;
        for (int c = lane; c < M_KV; c += 32) mx = fmaxf(mx, S[r * SSW + c]);
#pragma unroll
        for (int o = 16; o; o >>= 1) mx = fmaxf(mx, __shfl_xor_sync(0xffffffffu, mx, o));
        float sum = 0.f;
        float ev[5];
#pragma unroll
        for (int t = 0; t < 5; t++) {
            int c = lane + t * 32;
            float e = (c < M_KV) ? expf(S[r * SSW + c] - mx) : 0.f;
            ev[t] = e;
            sum += e;
        }
#pragma unroll
        for (int o = 16; o; o >>= 1) sum += __shfl_xor_sync(0xffffffffu, sum, o);
        float inv = 1.0f / sum;
#pragma unroll
        for (int t = 0; t < 5; t++) {
            int c = lane + t * 32;
            if (c < M_KV) ph[r * PVH + c] = __float2half_rn(ev[t] * inv);
        }
    }
    __syncthreads();

    // ---- PV: O[i][d] = sum_j P[i][j] v[j][d]; K = 144 -> 9 x k16
    float acc2[4][4];
#pragma unroll
    for (int nt = 0; nt < 4; nt++)
#pragma unroll
        for (int r = 0; r < 4; r++) acc2[nt][r] = 0.f;

    {
        const uint32_t pB = s2u(ph) + (uint32_t)((wm * 16 + lo7 + 8 * l3) * 304);
        const uint32_t vB = s2u(vh) + (uint32_t)((wn * 32 + lo7) * 304);
#pragma unroll
        for (int ks = 0; ks < 9; ks++) {
            uint32_t a[4];
            ldsm_x4(a, pB + (uint32_t)(ks * 32 + 16 * hi));
#pragma unroll
            for (int nt = 0; nt < 4; nt++) {
                uint32_t bfr[2];
                ldsm_x2(bfr, vB + (uint32_t)(nt * 8 * 304 + ks * 32 + 16 * l3));
                mma_f16(acc2[nt], a, bfr);
            }
        }
    }

    // ---- row 64 scalar PV
    float o64 = 0.f;
    if (tid < HDIM) {
        for (int j = 0; j < M_KV; j++)
            o64 += __half2float(ph[64 * PVH + j]) * __half2float(vh[tid * PVH + j]);
    }

    // ---- write output (fp16) rows 0..63
#pragma unroll
    for (int nt = 0; nt < 4; nt++) {
        int i0 = wm * 16 + quad;
        int d0 = wn * 32 + nt * 8 + 2 * tq;
        *(uint32_t*)&out[((size_t)(b * N_Q + i0)) * CDIM + h * HDIM + d0] =
            h2u(__floats2half2_rn(acc2[nt][0], acc2[nt][1]));
        *(uint32_t*)&out[((size_t)(b * N_Q + i0 + 8)) * CDIM + h * HDIM + d0] =
            h2u(__floats2half2_rn(acc2[nt][2], acc2[nt][3]));
    }
    if (tid < HDIM)
        out[((size_t)(b * N_Q + 64)) * CDIM + h * HDIM + tid] = __float2half_rn(o64);
}

// =======================================================================
// kernel_launch
// =======================================================================
extern "C" void kernel_launch(void* const* d_in, const int* in_sizes, int n_in,
                              void* d_out, int out_size)
{
    const float* x    = (const float*)d_in[0];
    const float* x_   = (const float*)d_in[1];
    const int*   mask_left  = (const int*)d_in[2];
    const int*   mask_right = (const int*)d_in[3];
    const int*   nW   = (const int*)d_in[4];
    const float* rel_table = (const float*)d_in[5];
    const float* cls_self  = (const float*)d_in[6];
    const float* cls_up    = (const float*)d_in[7];
    const float* cls_down  = (const float*)d_in[8];
    const float* Wq   = (const float*)d_in[9];
    const float* bq   = (const float*)d_in[10];
    const float* Wkv  = (const float*)d_in[11];
    const float* bkv  = (const float*)d_in[12];
    const float* Wp   = (const float*)d_in[13];
    const float* bp   = (const float*)d_in[14];
    float* out = (float*)d_out;

    const int Bq = in_sizes[0] / (N_Q * CDIM);   // 512

    __half *hx, *hx_, *hwq, *hwkv, *hwp, *hq, *hkv, *hatt;
    cudaGetSymbolAddress((void**)&hx,   h_x);
    cudaGetSymbolAddress((void**)&hx_,  h_x_);
    cudaGetSymbolAddress((void**)&hwq,  h_wq);
    cudaGetSymbolAddress((void**)&hwkv, h_wkv);
    cudaGetSymbolAddress((void**)&hwp,  h_wp);
    cudaGetSymbolAddress((void**)&hq,   h_q);
    cudaGetSymbolAddress((void**)&hkv,  h_kv);
    cudaGetSymbolAddress((void**)&hatt, h_att);

    cudaFuncSetAttribute(gemm_f16_kernel,
                         cudaFuncAttributeMaxDynamicSharedMemorySize,
                         GEMM_SMEM_BYTES);
    cudaFuncSetAttribute(attn_kernel,
                         cudaFuncAttributeMaxDynamicSharedMemorySize,
                         ATTN_SMEM_BYTES);

    // 0) fp32 -> fp16 pre-pass
    {
        int n;
        n = Bq * N_Q * CDIM / 8;
        cvt_fp16_kernel<<<(n + 255) / 256, 256>>>(x, hx, n);
        n = Bq * M_KV * CDIM / 8;
        cvt_fp16_kernel<<<(n + 255) / 256, 256>>>(x_, hx_, n);
        n = CDIM * CDIM / 8;
        cvt_fp16_kernel<<<(n + 255) / 256, 256>>>(Wq, hwq, n);
        n = 2 * CDIM * CDIM / 8;
        cvt_fp16_kernel<<<(n + 255) / 256, 256>>>(Wkv, hwkv, n);
        n = CDIM * CDIM / 8;
        cvt_fp16_kernel<<<(n + 255) / 256, 256>>>(Wp, hwp, n);
    }

    // 1) q = x @ Wq^T + bq : M = 33280, N = 512, K = 512   -> fp16
    {
        dim3 grid(CDIM / GBN, (Bq * N_Q) / GBM);
        gemm_f16_kernel<<<grid, 256, GEMM_SMEM_BYTES>>>(
            hx, hwq, bq, hq, CDIM, CDIM, 1);
    }
    // 2) kv = x_ @ Wkv^T + bkv : M = 66048, N = 1024, K = 512 -> fp16
    {
        dim3 grid((2 * CDIM) / GBN, (Bq * M_KV) / GBM);
        gemm_f16_kernel<<<grid, 256, GEMM_SMEM_BYTES>>>(
            hx_, hwkv, bkv, hkv, CDIM, 2 * CDIM, 1);
    }
    // 3) fused fp16 attention -> h_att
    {
        attn_kernel<<<Bq * NH, 256, ATTN_SMEM_BYTES>>>(
            rel_table, cls_self, cls_up, cls_down,
            mask_left, mask_right, nW, hatt);
    }
    // 4) out = att @ Wp^T + bp : M = 33280, N = 512, K = 512 -> fp32
    {
        dim3 grid(CDIM / GBN, (Bq * N_Q) / GBM);
        gemm_f16_kernel<<<grid, 256, GEMM_SMEM_BYTES>>>(
            hatt, hwp, bp, out, CDIM, CDIM, 0);
    }
}

// round 12
// speedup vs baseline: 2.0475x; 1.1624x over previous
#include <cuda_runtime.h>
#include <cuda_fp16.h>
#include <math.h>
#include <float.h>
#include <stdint.h>

// ---------------- problem constants (fixed by dataset) ----------------
#define N_Q   65      // n = 1+W
#define M_KV  129     // m = 1+R
#define NH    8       // heads
#define HDIM  64      // head dim
#define CDIM  512     // model dim (= H*HD)
#define BQMAX 512     // B_ = 512

// ---------------- scratch (device globals; no allocation) -------------
__device__ __half h_x  [(size_t)BQMAX * N_Q  * CDIM];
__device__ __half h_x_ [(size_t)BQMAX * M_KV * CDIM];
__device__ __half h_wq [(size_t)CDIM * CDIM];
__device__ __half h_wkv[(size_t)2 * CDIM * CDIM];
__device__ __half h_wp [(size_t)CDIM * CDIM];
__device__ __half h_q  [(size_t)BQMAX * N_Q  * CDIM];
__device__ __half h_kv [(size_t)BQMAX * M_KV * 2 * CDIM];
__device__ __half h_att[(size_t)BQMAX * N_Q  * CDIM];

// ---------------- helpers ----------------------------------------------
__device__ __forceinline__ void mma_f16(float c[4], const uint32_t a[4],
                                        const uint32_t b[2]) {
    asm volatile(
        "mma.sync.aligned.m16n8k16.row.col.f32.f16.f16.f32 "
        "{%0,%1,%2,%3}, {%4,%5,%6,%7}, {%8,%9}, {%0,%1,%2,%3};"
        : "+f"(c[0]), "+f"(c[1]), "+f"(c[2]), "+f"(c[3])
        : "r"(a[0]), "r"(a[1]), "r"(a[2]), "r"(a[3]),
          "r"(b[0]), "r"(b[1]));
}
__device__ __forceinline__ void cp16(void* smem, const void* g) {
    uint32_t a = (uint32_t)__cvta_generic_to_shared(smem);
    asm volatile("cp.async.cg.shared.global [%0], [%1], 16;\n"
                 :: "r"(a), "l"(g));
}
__device__ __forceinline__ uint32_t h2u(__half2 h) {
    return *reinterpret_cast<uint32_t*>(&h);
}
__device__ __forceinline__ uint32_t s2u(const void* p) {
    return (uint32_t)__cvta_generic_to_shared(p);
}
__device__ __forceinline__ void ldsm_x4(uint32_t r[4], uint32_t addr) {
    asm volatile("ldmatrix.sync.aligned.m8n8.x4.shared.b16 {%0,%1,%2,%3}, [%4];"
                 : "=r"(r[0]), "=r"(r[1]), "=r"(r[2]), "=r"(r[3]) : "r"(addr));
}
__device__ __forceinline__ void ldsm_x2(uint32_t r[2], uint32_t addr) {
    asm volatile("ldmatrix.sync.aligned.m8n8.x2.shared.b16 {%0,%1}, [%2];"
                 : "=r"(r[0]), "=r"(r[1]) : "r"(addr));
}

// =======================================================================
// fp32 -> fp16 conversion pre-pass, all 5 tensors in ONE launch.
// Unit of work = 8 elements.
// =======================================================================
__global__ void cvt_fp16_multi(
    const float* __restrict__ s0, __half* __restrict__ d0, int n0,
    const float* __restrict__ s1, __half* __restrict__ d1, int n1,
    const float* __restrict__ s2, __half* __restrict__ d2, int n2,
    const float* __restrict__ s3, __half* __restrict__ d3, int n3,
    const float* __restrict__ s4, __half* __restrict__ d4, int n4)
{
    int i = blockIdx.x * blockDim.x + threadIdx.x;
    const float* s; __half* d; int l = i;
    if (l < n0)                  { s = s0; d = d0; }
    else if ((l -= n0) < n1)     { s = s1; d = d1; }
    else if ((l -= n1) < n2)     { s = s2; d = d2; }
    else if ((l -= n2) < n3)     { s = s3; d = d3; }
    else if ((l -= n3) < n4)     { s = s4; d = d4; }
    else return;
    const float4 v0 = ((const float4*)s)[l * 2];
    const float4 v1 = ((const float4*)s)[l * 2 + 1];
    uint4 o;
    o.x = h2u(__floats2half2_rn(v0.x, v0.y));
    o.y = h2u(__floats2half2_rn(v0.z, v0.w));
    o.z = h2u(__floats2half2_rn(v1.x, v1.y));
    o.w = h2u(__floats2half2_rn(v1.z, v1.w));
    ((uint4*)d)[l] = o;
}

// =======================================================================
// FP16 tensor-core GEMM, cp.async 2-stage, SW128-swizzled smem, ldmatrix.
//   C[M,N] = A[M,K] @ W[N,K]^T + bias[N]   (A, W fp16; accum/bias fp32)
// BM=128, BN=128, BK=64, 256 threads (8 warps = 2(M) x 4(N)),
// warp tile 64x32 (4x4 m16n8k16). Requires M%128==0, N%128==0, K%64==0.
// =======================================================================
#define GBM 128
#define GBN 128
#define GBK 64
#define TILE_B   (128 * 128)
#define STAGE_B  (2 * TILE_B)
#define GEMM_SMEM_BYTES (2 * STAGE_B)         // 65536

__global__ __launch_bounds__(256, 2) void gemm_f16_kernel(
    const __half* __restrict__ A, const __half* __restrict__ W,
    const float* __restrict__ bias, void* __restrict__ Cv,
    int K, int N, int outHalf)
{
    extern __shared__ char smem[];

    const int tid    = threadIdx.x;
    const int warp   = tid >> 5;
    const int lane   = tid & 31;
    const int quad   = lane >> 2;
    const int tq     = lane & 3;
    const int lo7    = lane & 7;
    const int l3     = (lane >> 3) & 1;
    const int hi     = lane >> 4;
    const int warp_m = warp >> 2;
    const int warp_n = warp & 3;
    const int rowBase = blockIdx.y * GBM;
    const int colBase = blockIdx.x * GBN;

    const __half* Ap = A + (size_t)rowBase * K;
    const __half* Wp = W + (size_t)colBase * K;

    float acc[4][4][4];
#pragma unroll
    for (int mt = 0; mt < 4; mt++)
#pragma unroll
        for (int nt = 0; nt < 4; nt++)
#pragma unroll
            for (int r = 0; r < 4; r++) acc[mt][nt][r] = 0.f;

    const uint32_t sbase = s2u(smem);
    const uint32_t aRow = (uint32_t)((warp_m * 64 + lo7 + 8 * l3) * 128);
    const uint32_t bRow = (uint32_t)((warp_n * 32 + lo7) * 128);

    const int NITER = K >> 6;

    auto issue = [&](int it) {
        char* aS = smem + (it & 1) * STAGE_B;
        char* bS = aS + TILE_B;
        const int k0 = it * GBK;
#pragma unroll
        for (int i = 0; i < 4; i++) {
            int f   = tid + i * 256;
            int r   = f >> 3;
            int seg = f & 7;
            int dst = r * 128 + ((seg ^ (r & 7)) * 16);
            cp16(aS + dst, Ap + (size_t)r * K + k0 + seg * 8);
            cp16(bS + dst, Wp + (size_t)r * K + k0 + seg * 8);
        }
    };

    issue(0);
    asm volatile("cp.async.commit_group;\n");

    for (int it = 0; it < NITER; it++) {
        if (it + 1 < NITER) {
            issue(it + 1);
            asm volatile("cp.async.commit_group;\n");
            asm volatile("cp.async.wait_group 1;\n");
        } else {
            asm volatile("cp.async.wait_group 0;\n");
        }
        __syncthreads();

        const uint32_t aBase = sbase + (it & 1) * STAGE_B;
        const uint32_t bBase = aBase + TILE_B;

#pragma unroll
        for (int ks = 0; ks < 4; ks++) {
            const uint32_t aSeg = (uint32_t)(((2 * ks + hi) ^ lo7) * 16);
            const uint32_t bSeg = (uint32_t)(((2 * ks + l3) ^ lo7) * 16);
            uint32_t af[4][4];
            uint32_t bf[4][2];
#pragma unroll
            for (int mt = 0; mt < 4; mt++)
                ldsm_x4(af[mt], aBase + aRow + (uint32_t)(mt * 16 * 128) + aSeg);
#pragma unroll
            for (int nt = 0; nt < 4; nt++)
                ldsm_x2(bf[nt], bBase + bRow + (uint32_t)(nt * 8 * 128) + bSeg);
#pragma unroll
            for (int mt = 0; mt < 4; mt++)
#pragma unroll
                for (int nt = 0; nt < 4; nt++)
                    mma_f16(acc[mt][nt], af[mt], bf[nt]);
        }
        __syncthreads();
    }

#pragma unroll
    for (int mt = 0; mt < 4; mt++) {
        int r0 = rowBase + warp_m * 64 + mt * 16 + quad;
#pragma unroll
        for (int nt = 0; nt < 4; nt++) {
            int c = colBase + warp_n * 32 + nt * 8 + 2 * tq;
            float2 bv = *(const float2*)&bias[c];
            float ox0 = acc[mt][nt][0] + bv.x;
            float oy0 = acc[mt][nt][1] + bv.y;
            float ox1 = acc[mt][nt][2] + bv.x;
            float oy1 = acc[mt][nt][3] + bv.y;
            if (outHalf) {
                __half* Ch = (__half*)Cv;
                *(uint32_t*)&Ch[(size_t)r0 * N + c] =
                    h2u(__floats2half2_rn(ox0, oy0));
                *(uint32_t*)&Ch[(size_t)(r0 + 8) * N + c] =
                    h2u(__floats2half2_rn(ox1, oy1));
            } else {
                float* Cf = (float*)Cv;
                *(float2*)&Cf[(size_t)r0 * N + c]       = make_float2(ox0, oy0);
                *(float2*)&Cf[(size_t)(r0 + 8) * N + c] = make_float2(ox1, oy1);
            }
        }
    }
}

// =======================================================================
// FP16 fused window attention with ldmatrix fragments.
//   R1 [0, 4940):      q fp16 [65][72h] -> P fp16 [65][152h] (overlay)
//   R2 [4940, 10124):  k fp16 [144][72h] -> v^T fp16 [64][152h] (overlay)
//   S  [10124, 18704): S fp32 [65][132]
//   tables [18704, 19088)
// 76,352 B/CTA -> target 3 CTAs/SM.
// =======================================================================
#define QKH 72
#define PVH 152
#define SSW 132
#define R1_W   4940
#define R2_W   5184
#define OFF_S  (R1_W + R2_W)
#define OFF_BR (OFF_S + N_Q * SSW)
#define OFF_BU (OFF_BR + 191)
#define OFF_BD (OFF_BU + 128)
#define OFF_BSF (OFF_BD + 64)
#define ATTN_W (OFF_BSF + 1)
#define ATTN_SMEM_BYTES (ATTN_W * 4)

__global__ __launch_bounds__(256, 3) void attn_kernel(
    const float* __restrict__ rel_table,
    const float* __restrict__ cls_self,
    const float* __restrict__ cls_up,
    const float* __restrict__ cls_down,
    const int*   __restrict__ mask_left,
    const int*   __restrict__ mask_right,
    const int*   __restrict__ nW_ptr,
    __half* __restrict__ out)
{
    extern __shared__ float sm[];
    __half* qh  = (__half*)sm;
    __half* ph  = (__half*)sm;
    __half* kh  = (__half*)(sm + R1_W);
    __half* vh  = (__half*)(sm + R1_W);
    float*  S   = sm + OFF_S;
    float*  brl = sm + OFF_BR;
    float*  bup = sm + OFF_BU;
    float*  bdn = sm + OFF_BD;
    float*  bsf = sm + OFF_BSF;

    const int bid  = blockIdx.x;
    const int b    = bid >> 3;
    const int h    = bid & 7;
    const int tid  = threadIdx.x;
    const int warp = tid >> 5;
    const int lane = tid & 31;
    const int quad = lane >> 2;
    const int tq   = lane & 3;
    const int lo7  = lane & 7;
    const int l3   = (lane >> 3) & 1;
    const int hi   = lane >> 4;
    const int wm   = warp >> 1;
    const int wn   = warp & 1;
    const int nW   = *nW_ptr;

    if (tid < 191) brl[tid] = rel_table[tid * NH + h];
    if (tid < 128) bup[tid] = cls_up[h * 128 + tid];
    if (tid < 64)  bdn[tid] = cls_down[h * 64 + tid];
    if (tid == 224) bsf[0]  = cls_self[h];

    for (int idx = tid; idx < N_Q * 8; idx += 256) {
        int i = idx >> 3, c = idx & 7;
        uint4 v = *(const uint4*)&h_q[((size_t)(b * N_Q + i)) * CDIM + h * HDIM + c * 8];
        *(uint4*)&qh[i * QKH + c * 8] = v;
    }
    for (int idx = tid; idx < 144 * 8; idx += 256) {
        int j = idx >> 3, c = idx & 7;
        uint4 v = {0u, 0u, 0u, 0u};
        if (j < M_KV)
            v = *(const uint4*)&h_kv[((size_t)(b * M_KV + j)) * (2 * CDIM)
                                     + h * HDIM + c * 8];
        *(uint4*)&kh[j * QKH + c * 8] = v;
    }
    __syncthreads();

    // ---- QK^T: rows 0..63, 9 n-tiles per warp half
    const int nbase = wn * 72;
    float acc[9][4];
#pragma unroll
    for (int nt = 0; nt < 9; nt++)
#pragma unroll
        for (int r = 0; r < 4; r++) acc[nt][r] = 0.f;

    {
        const uint32_t qB = s2u(qh) + (uint32_t)((wm * 16 + lo7 + 8 * l3) * 144);
        const uint32_t kB = s2u(kh) + (uint32_t)((nbase + lo7) * 144);
#pragma unroll
        for (int ks = 0; ks < 4; ks++) {
            uint32_t a[4];
            ldsm_x4(a, qB + (uint32_t)(ks * 32 + 16 * hi));
#pragma unroll
            for (int nt = 0; nt < 9; nt++) {
                uint32_t bfr[2];
                ldsm_x2(bfr, kB + (uint32_t)(nt * 8 * 144 + ks * 32 + 16 * l3));
                mma_f16(acc[nt], a, bfr);
            }
        }
    }

    // ---- row 64 scalar logits
    float s64 = 0.f;
    if (tid < M_KV) {
#pragma unroll 8
        for (int d = 0; d < HDIM; d++)
            s64 += __half2float(qh[64 * QKH + d]) * __half2float(kh[tid * QKH + d]);
    }
    __syncthreads();

    const int mc   = (nW < 4) ? nW : 4;
    const int w    = b % nW;
    const bool hasL = (w < mc);
    const bool hasR = (w >= nW - mc);
    const int* mlp = mask_left  + (size_t)w * N_Q * M_KV;
    const int* mrp = mask_right + (size_t)(w - nW + 4) * N_Q * M_KV;

#pragma unroll
    for (int nt = 0; nt < 9; nt++) {
        int j0 = nbase + nt * 8 + 2 * tq;
        int i0 = wm * 16 + quad;
#pragma unroll
        for (int e = 0; e < 4; e++) {
            int i = i0 + (e >> 1) * 8;
            int j = j0 + (e & 1);
            if (j >= M_KV) continue;
            float bias;
            if (i == 0)      bias = (j == 0) ? bsf[0] : bup[j - 1];
            else if (j == 0) bias = bdn[i - 1];
            else             bias = brl[i - j + 127];
            float s = acc[nt][e] * 0.125f + bias;
            if (hasL && mlp[i * M_KV + j] == 1) s = -FLT_MAX;
            if (hasR && mrp[i * M_KV + j] == 1) s = -FLT_MAX;
            S[i * SSW + j] = s;
        }
    }
    if (tid < M_KV) {
        int j = tid;
        float bias = (j == 0) ? bdn[63] : brl[64 - j + 127];
        float s = s64 * 0.125f + bias;
        if (hasL && mlp[64 * M_KV + j] == 1) s = -FLT_MAX;
        if (hasR && mrp[64 * M_KV + j] == 1) s = -FLT_MAX;
        S[64 * SSW + j] = s;
    }

    for (int idx = tid; idx < N_Q * 15; idx += 256) {
        int i = idx / 15, c = M_KV + idx % 15;
        ph[i * PVH + c] = __float2half(0.f);
    }
    for (int idx = tid; idx < 144 * HDIM; idx += 256) {
        int j = idx >> 6, d = idx & 63;
        __half v = __float2half(0.f);
        if (j < M_KV)
            v = h_kv[((size_t)(b * M_KV + j)) * (2 * CDIM) + CDIM + h * HDIM + d];
        vh[d * PVH + j] = v;
    }
    __syncthreads();

    // ---- softmax rows 0..64 (fast __expf), write fp16 P
    for (int r = warp; r < N_Q; r += 8) {
        float mx = -FLT_MAX;
        for (int c = lane; c < M_KV; c += 32) mx = fmaxf(mx, S[r * SSW + c]);
#pragma unroll
        for (int o = 16; o; o >>= 1) mx = fmaxf(mx, __shfl_xor_sync(0xffffffffu, mx, o));
        float sum = 0.f;
        float ev[5];
#pragma unroll
        for (int t = 0; t < 5; t++) {
            int c = lane + t * 32;
            float e = (c < M_KV) ? __expf(S[r * SSW + c] - mx) : 0.f;
            ev[t] = e;
            sum += e;
        }
#pragma unroll
        for (int o = 16; o; o >>= 1) sum += __shfl_xor_sync(0xffffffffu, sum, o);
        float inv = 1.0f / sum;
#pragma unroll
        for (int t = 0; t < 5; t++) {
            int c = lane + t * 32;
            if (c < M_KV) ph[r * PVH + c] = __float2half_rn(ev[t] * inv);
        }
    }
    __syncthreads();

    // ---- PV: K = 144 -> 9 x k16
    float acc2[4][4];
#pragma unroll
    for (int nt = 0; nt < 4; nt++)
#pragma unroll
        for (int r = 0; r < 4; r++) acc2[nt][r] = 0.f;

    {
        const uint32_t pB = s2u(ph) + (uint32_t)((wm * 16 + lo7 + 8 * l3) * 304);
        const uint32_t vB = s2u(vh) + (uint32_t)((wn * 32 + lo7) * 304);
#pragma unroll
        for (int ks = 0; ks < 9; ks++) {
            uint32_t a[4];
            ldsm_x4(a, pB + (uint32_t)(ks * 32 + 16 * hi));
#pragma unroll
            for (int nt = 0; nt < 4; nt++) {
                uint32_t bfr[2];
                ldsm_x2(bfr, vB + (uint32_t)(nt * 8 * 304 + ks * 32 + 16 * l3));
                mma_f16(acc2[nt], a, bfr);
            }
        }
    }

    // ---- row 64 scalar PV
    float o64 = 0.f;
    if (tid < HDIM) {
        for (int j = 0; j < M_KV; j++)
            o64 += __half2float(ph[64 * PVH + j]) * __half2float(vh[tid * PVH + j]);
    }

#pragma unroll
    for (int nt = 0; nt < 4; nt++) {
        int i0 = wm * 16 + quad;
        int d0 = wn * 32 + nt * 8 + 2 * tq;
        *(uint32_t*)&out[((size_t)(b * N_Q + i0)) * CDIM + h * HDIM + d0] =
            h2u(__floats2half2_rn(acc2[nt][0], acc2[nt][1]));
        *(uint32_t*)&out[((size_t)(b * N_Q + i0 + 8)) * CDIM + h * HDIM + d0] =
            h2u(__floats2half2_rn(acc2[nt][2], acc2[nt][3]));
    }
    if (tid < HDIM)
        out[((size_t)(b * N_Q + 64)) * CDIM + h * HDIM + tid] = __float2half_rn(o64);
}

// =======================================================================
// kernel_launch
// =======================================================================
extern "C" void kernel_launch(void* const* d_in, const int* in_sizes, int n_in,
                              void* d_out, int out_size)
{
    const float* x    = (const float*)d_in[0];
    const float* x_   = (const float*)d_in[1];
    const int*   mask_left  = (const int*)d_in[2];
    const int*   mask_right = (const int*)d_in[3];
    const int*   nW   = (const int*)d_in[4];
    const float* rel_table = (const float*)d_in[5];
    const float* cls_self  = (const float*)d_in[6];
    const float* cls_up    = (const float*)d_in[7];
    const float* cls_down  = (const float*)d_in[8];
    const float* Wq   = (const float*)d_in[9];
    const float* bq   = (const float*)d_in[10];
    const float* Wkv  = (const float*)d_in[11];
    const float* bkv  = (const float*)d_in[12];
    const float* Wp   = (const float*)d_in[13];
    const float* bp   = (const float*)d_in[14];
    float* out = (float*)d_out;

    const int Bq = in_sizes[0] / (N_Q * CDIM);   // 512

    __half *hx, *hx_, *hwq, *hwkv, *hwp, *hq, *hkv, *hatt;
    cudaGetSymbolAddress((void**)&hx,   h_x);
    cudaGetSymbolAddress((void**)&hx_,  h_x_);
    cudaGetSymbolAddress((void**)&hwq,  h_wq);
    cudaGetSymbolAddress((void**)&hwkv, h_wkv);
    cudaGetSymbolAddress((void**)&hwp,  h_wp);
    cudaGetSymbolAddress((void**)&hq,   h_q);
    cudaGetSymbolAddress((void**)&hkv,  h_kv);
    cudaGetSymbolAddress((void**)&hatt, h_att);

    cudaFuncSetAttribute(gemm_f16_kernel,
                         cudaFuncAttributeMaxDynamicSharedMemorySize,
                         GEMM_SMEM_BYTES);
    cudaFuncSetAttribute(attn_kernel,
                         cudaFuncAttributeMaxDynamicSharedMemorySize,
                         ATTN_SMEM_BYTES);

    // 0) fp32 -> fp16 pre-pass (single launch, 5 tensors)
    {
        int n0 = Bq * N_Q * CDIM / 8;
        int n1 = Bq * M_KV * CDIM / 8;
        int n2 = CDIM * CDIM / 8;
        int n3 = 2 * CDIM * CDIM / 8;
        int n4 = CDIM * CDIM / 8;
        int total = n0 + n1 + n2 + n3 + n4;
        cvt_fp16_multi<<<(total + 255) / 256, 256>>>(
            x, hx, n0, x_, hx_, n1, Wq, hwq, n2, Wkv, hwkv, n3, Wp, hwp, n4);
    }

    // 1) q = x @ Wq^T + bq : M = 33280, N = 512, K = 512   -> fp16
    {
        dim3 grid(CDIM / GBN, (Bq * N_Q) / GBM);
        gemm_f16_kernel<<<grid, 256, GEMM_SMEM_BYTES>>>(
            hx, hwq, bq, hq, CDIM, CDIM, 1);
    }
    // 2) kv = x_ @ Wkv^T + bkv : M = 66048, N = 1024, K = 512 -> fp16
    {
        dim3 grid((2 * CDIM) / GBN, (Bq * M_KV) / GBM);
        gemm_f16_kernel<<<grid, 256, GEMM_SMEM_BYTES>>>(
            hx_, hwkv, bkv, hkv, CDIM, 2 * CDIM, 1);
    }
    // 3) fused fp16 attention -> h_att
    {
        attn_kernel<<<Bq * NH, 256, ATTN_SMEM_BYTES>>>(
            rel_table, cls_self, cls_up, cls_down,
            mask_left, mask_right, nW, hatt);
    }
    // 4) out = att @ Wp^T + bp : M = 33280, N = 512, K = 512 -> fp32
    {
        dim3 grid(CDIM / GBN, (Bq * N_Q) / GBM);
        gemm_f16_kernel<<<grid, 256, GEMM_SMEM_BYTES>>>(
            hatt, hwp, bp, out, CDIM, CDIM, 0);
    }
}

// round 13
// speedup vs baseline: 2.0590x; 1.0056x over previous
#include <cuda_runtime.h>
#include <cuda_fp16.h>
#include <math.h>
#include <float.h>
#include <stdint.h>

// ---------------- problem constants (fixed by dataset) ----------------
#define N_Q   65      // n = 1+W
#define M_KV  129     // m = 1+R
#define NH    8       // heads
#define HDIM  64      // head dim
#define CDIM  512     // model dim (= H*HD)
#define BQMAX 512     // B_ = 512

// ---------------- scratch (device globals; no allocation) -------------
__device__ __half h_x  [(size_t)BQMAX * N_Q  * CDIM];
__device__ __half h_x_ [(size_t)BQMAX * M_KV * CDIM];
__device__ __half h_wq [(size_t)CDIM * CDIM];
__device__ __half h_wkv[(size_t)2 * CDIM * CDIM];
__device__ __half h_wp [(size_t)CDIM * CDIM];
__device__ __half h_q  [(size_t)BQMAX * N_Q  * CDIM];
__device__ __half h_kv [(size_t)BQMAX * M_KV * 2 * CDIM];
__device__ __half h_att[(size_t)BQMAX * N_Q  * CDIM];
// bias+mask tables: 9 window classes x 8 heads x 65 x 132 fp32
__device__ float g_bias[(size_t)9 * NH * N_Q * 132];

// ---------------- helpers ----------------------------------------------
__device__ __forceinline__ void mma_f16(float c[4], const uint32_t a[4],
                                        const uint32_t b[2]) {
    asm volatile(
        "mma.sync.aligned.m16n8k16.row.col.f32.f16.f16.f32 "
        "{%0,%1,%2,%3}, {%4,%5,%6,%7}, {%8,%9}, {%0,%1,%2,%3};"
        : "+f"(c[0]), "+f"(c[1]), "+f"(c[2]), "+f"(c[3])
        : "r"(a[0]), "r"(a[1]), "r"(a[2]), "r"(a[3]),
          "r"(b[0]), "r"(b[1]));
}
__device__ __forceinline__ void cp16(void* smem, const void* g) {
    uint32_t a = (uint32_t)__cvta_generic_to_shared(smem);
    asm volatile("cp.async.cg.shared.global [%0], [%1], 16;\n"
                 :: "r"(a), "l"(g));
}
__device__ __forceinline__ uint32_t h2u(__half2 h) {
    return *reinterpret_cast<uint32_t*>(&h);
}
__device__ __forceinline__ uint32_t s2u(const void* p) {
    return (uint32_t)__cvta_generic_to_shared(p);
}
__device__ __forceinline__ void ldsm_x4(uint32_t r[4], uint32_t addr) {
    asm volatile("ldmatrix.sync.aligned.m8n8.x4.shared.b16 {%0,%1,%2,%3}, [%4];"
                 : "=r"(r[0]), "=r"(r[1]), "=r"(r[2]), "=r"(r[3]) : "r"(addr));
}
__device__ __forceinline__ void ldsm_x2(uint32_t r[2], uint32_t addr) {
    asm volatile("ldmatrix.sync.aligned.m8n8.x2.shared.b16 {%0,%1}, [%2];"
                 : "=r"(r[0]), "=r"(r[1]) : "r"(addr));
}
__device__ __forceinline__ void ldsm_x2_trans(uint32_t r[2], uint32_t addr) {
    asm volatile("ldmatrix.sync.aligned.m8n8.x2.trans.shared.b16 {%0,%1}, [%2];"
                 : "=r"(r[0]), "=r"(r[1]) : "r"(addr));
}

// =======================================================================
// fp32 -> fp16 conversion pre-pass, all 5 tensors in ONE launch.
// =======================================================================
__global__ void cvt_fp16_multi(
    const float* __restrict__ s0, __half* __restrict__ d0, int n0,
    const float* __restrict__ s1, __half* __restrict__ d1, int n1,
    const float* __restrict__ s2, __half* __restrict__ d2, int n2,
    const float* __restrict__ s3, __half* __restrict__ d3, int n3,
    const float* __restrict__ s4, __half* __restrict__ d4, int n4)
{
    int i = blockIdx.x * blockDim.x + threadIdx.x;
    const float* s; __half* d; int l = i;
    if (l < n0)                  { s = s0; d = d0; }
    else if ((l -= n0) < n1)     { s = s1; d = d1; }
    else if ((l -= n1) < n2)     { s = s2; d = d2; }
    else if ((l -= n2) < n3)     { s = s3; d = d3; }
    else if ((l -= n3) < n4)     { s = s4; d = d4; }
    else return;
    const float4 v0 = ((const float4*)s)[l * 2];
    const float4 v1 = ((const float4*)s)[l * 2 + 1];
    uint4 o;
    o.x = h2u(__floats2half2_rn(v0.x, v0.y));
    o.y = h2u(__floats2half2_rn(v0.z, v0.w));
    o.z = h2u(__floats2half2_rn(v1.x, v1.y));
    o.w = h2u(__floats2half2_rn(v1.z, v1.w));
    ((uint4*)d)[l] = o;
}

// =======================================================================
// bias+mask table build: 72 blocks = (cls 0..8) x (h 0..7), 256 threads.
// cls 0: unmasked; cls 1..4: left-mask w=cls-1; cls 5..8: right-mask r=cls-5.
// =======================================================================
__global__ void build_bias_kernel(
    const float* __restrict__ rel, const float* __restrict__ self_,
    const float* __restrict__ up,  const float* __restrict__ down,
    const int* __restrict__ ml,    const int* __restrict__ mr)
{
    const int cls = blockIdx.x >> 3;
    const int h   = blockIdx.x & 7;
    float* dst = g_bias + ((size_t)(cls * NH + h)) * N_Q * 132;
    for (int idx = threadIdx.x; idx < N_Q * M_KV; idx += 256) {
        int i = idx / M_KV, j = idx % M_KV;
        float bias;
        if (i == 0)      bias = (j == 0) ? self_[h] : up[h * 128 + (j - 1)];
        else if (j == 0) bias = down[h * 64 + (i - 1)];
        else             bias = rel[(i - j + 127) * NH + h];
        if (cls >= 1 && cls <= 4) {
            if (ml[((cls - 1) * N_Q + i) * M_KV + j] == 1) bias = -FLT_MAX;
        } else if (cls >= 5) {
            if (mr[((cls - 5) * N_Q + i) * M_KV + j] == 1) bias = -FLT_MAX;
        }
        dst[i * 132 + j] = bias;
    }
    // zero pad columns 129..131
    for (int idx = threadIdx.x; idx < N_Q * 3; idx += 256) {
        int i = idx / 3, c = M_KV + idx % 3;
        dst[i * 132 + c] = 0.f;
    }
}

// =======================================================================
// FP16 tensor-core GEMM, cp.async 2-stage, SW128-swizzled smem, ldmatrix.
//   C[M,N] = (A[M,K] @ W[N,K]^T + bias[N]) * outScale
// =======================================================================
#define GBM 128
#define GBN 128
#define GBK 64
#define TILE_B   (128 * 128)
#define STAGE_B  (2 * TILE_B)
#define GEMM_SMEM_BYTES (2 * STAGE_B)         // 65536

__global__ __launch_bounds__(256, 2) void gemm_f16_kernel(
    const __half* __restrict__ A, const __half* __restrict__ W,
    const float* __restrict__ bias, void* __restrict__ Cv,
    int K, int N, int outHalf, float outScale)
{
    extern __shared__ char smem[];

    const int tid    = threadIdx.x;
    const int warp   = tid >> 5;
    const int lane   = tid & 31;
    const int quad   = lane >> 2;
    const int tq     = lane & 3;
    const int lo7    = lane & 7;
    const int l3     = (lane >> 3) & 1;
    const int hi     = lane >> 4;
    const int warp_m = warp >> 2;
    const int warp_n = warp & 3;
    const int rowBase = blockIdx.y * GBM;
    const int colBase = blockIdx.x * GBN;

    const __half* Ap = A + (size_t)rowBase * K;
    const __half* Wp = W + (size_t)colBase * K;

    float acc[4][4][4];
#pragma unroll
    for (int mt = 0; mt < 4; mt++)
#pragma unroll
        for (int nt = 0; nt < 4; nt++)
#pragma unroll
            for (int r = 0; r < 4; r++) acc[mt][nt][r] = 0.f;

    const uint32_t sbase = s2u(smem);
    const uint32_t aRow = (uint32_t)((warp_m * 64 + lo7 + 8 * l3) * 128);
    const uint32_t bRow = (uint32_t)((warp_n * 32 + lo7) * 128);

    const int NITER = K >> 6;

    auto issue = [&](int it) {
        char* aS = smem + (it & 1) * STAGE_B;
        char* bS = aS + TILE_B;
        const int k0 = it * GBK;
#pragma unroll
        for (int i = 0; i < 4; i++) {
            int f   = tid + i * 256;
            int r   = f >> 3;
            int seg = f & 7;
            int dst = r * 128 + ((seg ^ (r & 7)) * 16);
            cp16(aS + dst, Ap + (size_t)r * K + k0 + seg * 8);
            cp16(bS + dst, Wp + (size_t)r * K + k0 + seg * 8);
        }
    };

    issue(0);
    asm volatile("cp.async.commit_group;\n");

    for (int it = 0; it < NITER; it++) {
        if (it + 1 < NITER) {
            issue(it + 1);
            asm volatile("cp.async.commit_group;\n");
            asm volatile("cp.async.wait_group 1;\n");
        } else {
            asm volatile("cp.async.wait_group 0;\n");
        }
        __syncthreads();

        const uint32_t aBase = sbase + (it & 1) * STAGE_B;
        const uint32_t bBase = aBase + TILE_B;

#pragma unroll
        for (int ks = 0; ks < 4; ks++) {
            const uint32_t aSeg = (uint32_t)(((2 * ks + hi) ^ lo7) * 16);
            const uint32_t bSeg = (uint32_t)(((2 * ks + l3) ^ lo7) * 16);
            uint32_t af[4][4];
            uint32_t bf[4][2];
#pragma unroll
            for (int mt = 0; mt < 4; mt++)
                ldsm_x4(af[mt], aBase + aRow + (uint32_t)(mt * 16 * 128) + aSeg);
#pragma unroll
            for (int nt = 0; nt < 4; nt++)
                ldsm_x2(bf[nt], bBase + bRow + (uint32_t)(nt * 8 * 128) + bSeg);
#pragma unroll
            for (int mt = 0; mt < 4; mt++)
#pragma unroll
                for (int nt = 0; nt < 4; nt++)
                    mma_f16(acc[mt][nt], af[mt], bf[nt]);
        }
        __syncthreads();
    }

#pragma unroll
    for (int mt = 0; mt < 4; mt++) {
        int r0 = rowBase + warp_m * 64 + mt * 16 + quad;
#pragma unroll
        for (int nt = 0; nt < 4; nt++) {
            int c = colBase + warp_n * 32 + nt * 8 + 2 * tq;
            float2 bv = *(const float2*)&bias[c];
            float ox0 = (acc[mt][nt][0] + bv.x) * outScale;
            float oy0 = (acc[mt][nt][1] + bv.y) * outScale;
            float ox1 = (acc[mt][nt][2] + bv.x) * outScale;
            float oy1 = (acc[mt][nt][3] + bv.y) * outScale;
            if (outHalf) {
                __half* Ch = (__half*)Cv;
                *(uint32_t*)&Ch[(size_t)r0 * N + c] =
                    h2u(__floats2half2_rn(ox0, oy0));
                *(uint32_t*)&Ch[(size_t)(r0 + 8) * N + c] =
                    h2u(__floats2half2_rn(ox1, oy1));
            } else {
                float* Cf = (float*)Cv;
                *(float2*)&Cf[(size_t)r0 * N + c]       = make_float2(ox0, oy0);
                *(float2*)&Cf[(size_t)(r0 + 8) * N + c] = make_float2(ox1, oy1);
            }
        }
    }
}

// =======================================================================
// FP16 fused window attention, table-driven bias/mask, trans-ldsm PV.
//   R1 [0, 4940):      q fp16 [65][72h] -> P fp16 [65][152h] (overlay)
//   R2 [4940, 10124):  k fp16 [144][72h] -> v fp16 [144][72h] (overlay)
//   S  [10124, 18704): S fp32 [65][132]  (preloaded with bias table)
// 74,816 B/CTA -> 3 CTAs/SM.
// =======================================================================
#define QKH 72
#define PVH 152
#define SSW 132
#define R1_W   4940
#define R2_W   5184
#define OFF_S  (R1_W + R2_W)
#define ATTN_W (OFF_S + N_Q * SSW)
#define ATTN_SMEM_BYTES (ATTN_W * 4)

__global__ __launch_bounds__(256, 3) void attn_kernel(
    const int* __restrict__ nW_ptr,
    __half* __restrict__ out)
{
    extern __shared__ float sm[];
    __half* qh  = (__half*)sm;
    __half* ph  = (__half*)sm;
    __half* kh  = (__half*)(sm + R1_W);
    __half* vh  = (__half*)(sm + R1_W);
    float*  S   = sm + OFF_S;

    const int bid  = blockIdx.x;
    const int b    = bid >> 3;
    const int h    = bid & 7;
    const int tid  = threadIdx.x;
    const int warp = tid >> 5;
    const int lane = tid & 31;
    const int quad = lane >> 2;
    const int tq   = lane & 3;
    const int lo7  = lane & 7;
    const int l3   = (lane >> 3) & 1;
    const int hi   = lane >> 4;
    const int wm   = warp >> 1;
    const int wn   = warp & 1;
    const int nW   = *nW_ptr;

    // ---- window class -> bias+mask table slice
    const int mc = (nW < 4) ? nW : 4;
    const int w  = b % nW;
    int cls = 0;
    if (w < mc)            cls = 1 + w;
    else if (w >= nW - mc) cls = 5 + (w - nW + 4);
    const float* T = g_bias + ((size_t)(cls * NH + h)) * N_Q * 132;

    // ---- preload bias table into S (coalesced float4)
    for (int idx = tid; idx < (N_Q * SSW) / 4; idx += 256)
        *(float4*)&S[idx * 4] = *(const float4*)&T[idx * 4];

    // ---- load q fp16 (65 x 64h)  [q already scaled by 0.125 in GEMM]
    for (int idx = tid; idx < N_Q * 8; idx += 256) {
        int i = idx >> 3, c = idx & 7;
        uint4 v = *(const uint4*)&h_q[((size_t)(b * N_Q + i)) * CDIM + h * HDIM + c * 8];
        *(uint4*)&qh[i * QKH + c * 8] = v;
    }
    // ---- load k fp16 (129 x 64h), zero rows 129..143
    for (int idx = tid; idx < 144 * 8; idx += 256) {
        int j = idx >> 3, c = idx & 7;
        uint4 v = {0u, 0u, 0u, 0u};
        if (j < M_KV)
            v = *(const uint4*)&h_kv[((size_t)(b * M_KV + j)) * (2 * CDIM)
                                     + h * HDIM + c * 8];
        *(uint4*)&kh[j * QKH + c * 8] = v;
    }
    __syncthreads();

    // ---- QK^T: rows 0..63, 9 n-tiles per warp half
    const int nbase = wn * 72;
    float acc[9][4];
#pragma unroll
    for (int nt = 0; nt < 9; nt++)
#pragma unroll
        for (int r = 0; r < 4; r++) acc[nt][r] = 0.f;

    {
        const uint32_t qB = s2u(qh) + (uint32_t)((wm * 16 + lo7 + 8 * l3) * 144);
        const uint32_t kB = s2u(kh) + (uint32_t)((nbase + lo7) * 144);
#pragma unroll
        for (int ks = 0; ks < 4; ks++) {
            uint32_t a[4];
            ldsm_x4(a, qB + (uint32_t)(ks * 32 + 16 * hi));
#pragma unroll
            for (int nt = 0; nt < 9; nt++) {
                uint32_t bfr[2];
                ldsm_x2(bfr, kB + (uint32_t)(nt * 8 * 144 + ks * 32 + 16 * l3));
                mma_f16(acc[nt], a, bfr);
            }
        }
    }

    // ---- row 64 scalar logits
    float s64 = 0.f;
    if (tid < M_KV) {
#pragma unroll 8
        for (int d = 0; d < HDIM; d++)
            s64 += __half2float(qh[64 * QKH + d]) * __half2float(kh[tid * QKH + d]);
    }
    __syncthreads();

    // ---- S = acc + table (bias already holds mask as -FLT_MAX)
#pragma unroll
    for (int nt = 0; nt < 9; nt++) {
        int j0 = nbase + nt * 8 + 2 * tq;
        int i0 = wm * 16 + quad;
#pragma unroll
        for (int e = 0; e < 4; e++) {
            int i = i0 + (e >> 1) * 8;
            int j = j0 + (e & 1);
            if (j >= M_KV) continue;
            S[i * SSW + j] = acc[nt][e] + S[i * SSW + j];
        }
    }
    if (tid < M_KV)
        S[64 * SSW + tid] = s64 + S[64 * SSW + tid];

    // ---- zero P pad cols 129..143
    for (int idx = tid; idx < N_Q * 15; idx += 256) {
        int i = idx / 15, c = M_KV + idx % 15;
        ph[i * PVH + c] = __float2half(0.f);
    }
    // ---- load v fp16 natural [j][d], zero rows 129..143 (reuses k region)
    for (int idx = tid; idx < 144 * 8; idx += 256) {
        int j = idx >> 3, c = idx & 7;
        uint4 v = {0u, 0u, 0u, 0u};
        if (j < M_KV)
            v = *(const uint4*)&h_kv[((size_t)(b * M_KV + j)) * (2 * CDIM)
                                     + CDIM + h * HDIM + c * 8];
        *(uint4*)&vh[j * QKH + c * 8] = v;
    }
    __syncthreads();

    // ---- softmax rows 0..64 (fast __expf), write fp16 P
    for (int r = warp; r < N_Q; r += 8) {
        float mx = -FLT_MAX;
        for (int c = lane; c < M_KV; c += 32) mx = fmaxf(mx, S[r * SSW + c]);
#pragma unroll
        for (int o = 16; o; o >>= 1) mx = fmaxf(mx, __shfl_xor_sync(0xffffffffu, mx, o));
        float sum = 0.f;
        float ev[5];
#pragma unroll
        for (int t = 0; t < 5; t++) {
            int c = lane + t * 32;
            float e = (c < M_KV) ? __expf(S[r * SSW + c] - mx) : 0.f;
            ev[t] = e;
            sum += e;
        }
#pragma unroll
        for (int o = 16; o; o >>= 1) sum += __shfl_xor_sync(0xffffffffu, sum, o);
        float inv = 1.0f / sum;
#pragma unroll
        for (int t = 0; t < 5; t++) {
            int c = lane + t * 32;
            if (c < M_KV) ph[r * PVH + c] = __float2half_rn(ev[t] * inv);
        }
    }
    __syncthreads();

    // ---- PV: K = 144 -> 9 x k16; B via ldmatrix.trans from v[j][d]
    float acc2[4][4];
#pragma unroll
    for (int nt = 0; nt < 4; nt++)
#pragma unroll
        for (int r = 0; r < 4; r++) acc2[nt][r] = 0.f;

    {
        const uint32_t pB = s2u(ph) + (uint32_t)((wm * 16 + lo7 + 8 * l3) * 304);
        const uint32_t vB = s2u(vh) + (uint32_t)((lane & 15) * 144 + wn * 64);
#pragma unroll
        for (int ks = 0; ks < 9; ks++) {
            uint32_t a[4];
            ldsm_x4(a, pB + (uint32_t)(ks * 32 + 16 * hi));
#pragma unroll
            for (int nt = 0; nt < 4; nt++) {
                uint32_t bfr[2];
                ldsm_x2_trans(bfr, vB + (uint32_t)(ks * 16 * 144 + nt * 16));
                mma_f16(acc2[nt], a, bfr);
            }
        }
    }

    // ---- row 64 scalar PV (v natural layout)
    float o64 = 0.f;
    if (tid < HDIM) {
        for (int j = 0; j < M_KV; j++)
            o64 += __half2float(ph[64 * PVH + j]) * __half2float(vh[j * QKH + tid]);
    }

#pragma unroll
    for (int nt = 0; nt < 4; nt++) {
        int i0 = wm * 16 + quad;
        int d0 = wn * 32 + nt * 8 + 2 * tq;
        *(uint32_t*)&out[((size_t)(b * N_Q + i0)) * CDIM + h * HDIM + d0] =
            h2u(__floats2half2_rn(acc2[nt][0], acc2[nt][1]));
        *(uint32_t*)&out[((size_t)(b * N_Q + i0 + 8)) * CDIM + h * HDIM + d0] =
            h2u(__floats2half2_rn(acc2[nt][2], acc2[nt][3]));
    }
    if (tid < HDIM)
        out[((size_t)(b * N_Q + 64)) * CDIM + h * HDIM + tid] = __float2half_rn(o64);
}

// =======================================================================
// kernel_launch
// =======================================================================
extern "C" void kernel_launch(void* const* d_in, const int* in_sizes, int n_in,
                              void* d_out, int out_size)
{
    const float* x    = (const float*)d_in[0];
    const float* x_   = (const float*)d_in[1];
    const int*   mask_left  = (const int*)d_in[2];
    const int*   mask_right = (const int*)d_in[3];
    const int*   nW   = (const int*)d_in[4];
    const float* rel_table = (const float*)d_in[5];
    const float* cls_self  = (const float*)d_in[6];
    const float* cls_up    = (const float*)d_in[7];
    const float* cls_down  = (const float*)d_in[8];
    const float* Wq   = (const float*)d_in[9];
    const float* bq   = (const float*)d_in[10];
    const float* Wkv  = (const float*)d_in[11];
    const float* bkv  = (const float*)d_in[12];
    const float* Wp   = (const float*)d_in[13];
    const float* bp   = (const float*)d_in[14];
    float* out = (float*)d_out;

    const int Bq = in_sizes[0] / (N_Q * CDIM);   // 512

    __half *hx, *hx_, *hwq, *hwkv, *hwp, *hq, *hkv, *hatt;
    cudaGetSymbolAddress((void**)&hx,   h_x);
    cudaGetSymbolAddress((void**)&hx_,  h_x_);
    cudaGetSymbolAddress((void**)&hwq,  h_wq);
    cudaGetSymbolAddress((void**)&hwkv, h_wkv);
    cudaGetSymbolAddress((void**)&hwp,  h_wp);
    cudaGetSymbolAddress((void**)&hq,   h_q);
    cudaGetSymbolAddress((void**)&hkv,  h_kv);
    cudaGetSymbolAddress((void**)&hatt, h_att);

    cudaFuncSetAttribute(gemm_f16_kernel,
                         cudaFuncAttributeMaxDynamicSharedMemorySize,
                         GEMM_SMEM_BYTES);
    cudaFuncSetAttribute(attn_kernel,
                         cudaFuncAttributeMaxDynamicSharedMemorySize,
                         ATTN_SMEM_BYTES);

    // 0a) bias+mask table build (independent of GEMMs)
    build_bias_kernel<<<9 * NH, 256>>>(rel_table, cls_self, cls_up, cls_down,
                                       mask_left, mask_right);
    // 0b) fp32 -> fp16 pre-pass (single launch, 5 tensors)
    {
        int n0 = Bq * N_Q * CDIM / 8;
        int n1 = Bq * M_KV * CDIM / 8;
        int n2 = CDIM * CDIM / 8;
        int n3 = 2 * CDIM * CDIM / 8;
        int n4 = CDIM * CDIM / 8;
        int total = n0 + n1 + n2 + n3 + n4;
        cvt_fp16_multi<<<(total + 255) / 256, 256>>>(
            x, hx, n0, x_, hx_, n1, Wq, hwq, n2, Wkv, hwkv, n3, Wp, hwp, n4);
    }

    // 1) q = (x @ Wq^T + bq) * 0.125 : M = 33280, N = 512, K = 512 -> fp16
    {
        dim3 grid(CDIM / GBN, (Bq * N_Q) / GBM);
        gemm_f16_kernel<<<grid, 256, GEMM_SMEM_BYTES>>>(
            hx, hwq, bq, hq, CDIM, CDIM, 1, 0.125f);
    }
    // 2) kv = x_ @ Wkv^T + bkv : M = 66048, N = 1024, K = 512 -> fp16
    {
        dim3 grid((2 * CDIM) / GBN, (Bq * M_KV) / GBM);
        gemm_f16_kernel<<<grid, 256, GEMM_SMEM_BYTES>>>(
            hx_, hwkv, bkv, hkv, CDIM, 2 * CDIM, 1, 1.0f);
    }
    // 3) fused fp16 attention -> h_att
    {
        attn_kernel<<<Bq * NH, 256, ATTN_SMEM_BYTES>>>(nW, hatt);
    }
    // 4) out = att @ Wp^T + bp : M = 33280, N = 512, K = 512 -> fp32
    {
        dim3 grid(CDIM / GBN, (Bq * N_Q) / GBM);
        gemm_f16_kernel<<<grid, 256, GEMM_SMEM_BYTES>>>(
            hatt, hwp, bp, out, CDIM, CDIM, 0, 1.0f);
    }
}